// round 5
// baseline (speedup 1.0000x reference)
#include <cuda_runtime.h>
#include <math.h>

// Problem constants
#define KB   8      // batch
#define KN   1024   // sequence length
#define KD   512    // model dim
#define KH   8      // heads
#define KDH  64     // dim per head
#define KQ   1536   // qkv columns

// ---------------------------------------------------------------------------
// Scratch (static __device__ arrays; allocation-free per harness rules)
// ---------------------------------------------------------------------------
__device__ __align__(16) float g_qkv [KB * KN * KQ];          // [B*N, 1536]
__device__ __align__(16) float g_attn[KB * KH * KN * KN];     // softmax(A) per (b,h)
__device__ __align__(16) float g_conv[KB * KH * KN * KN];     // C = conv-mix of A (no bias)
__device__ __align__(16) float g_u   [KB * KH * KN * KDH];    // U = C @ V
__device__ __align__(16) float g_y   [KB * KN * KD];          // assembled [b,n,(h d)]
__device__ __align__(16) float g_vsum[KB * KH * KDH];         // sum_m V[b,h,m,d]
__device__ __align__(16) float g_part[KB * KN * 36];          // per-(b,n) moment partials
__device__ __align__(16) float g_S   [36];                    // mean(A_h * A_h') upper-tri
__device__ float g_k0[KH];   // coefficient on Vsum
__device__ float g_k1[KH];   // coefficient on U

// ---------------------------------------------------------------------------
// Generic fp32 smem-tiled GEMM.
//   C[z] = alpha * A[z] (@ or @^T) B[z]  (+ bias)
//   A: row-major M x K (lda), B: row-major K x N (ldb) if !TB,
//      else B is row-major N x K (ldb) and used transposed.
//   Batch offsets: off = (z/HB)*s1 + (z%HB)*s2 for each of A,B,C.
// ---------------------------------------------------------------------------
template <int BM, int BN, int BK, int TM, int TN, bool TB, bool BIAS>
__global__ __launch_bounds__(256)
void gemm_kernel(const float* __restrict__ Ag, const float* __restrict__ Bg,
                 float* __restrict__ Cg, const float* __restrict__ bias,
                 int M, int Nn, int K, int lda, int ldb, int ldc,
                 int HB, long sA1, long sA2, long sB1, long sB2,
                 long sC1, long sC2, float alpha)
{
    constexpr int TCOLS = BN / TN;
    constexpr int NT    = (BM / TM) * (BN / TN);
    static_assert(NT == 256, "expect 256 threads");

    __shared__ __align__(16) float As[BK][BM];
    __shared__ __align__(16) float Bs[BK][BN];

    const int z = blockIdx.z;
    const float* A  = Ag + (long)(z / HB) * sA1 + (long)(z % HB) * sA2;
    const float* Bp = Bg + (long)(z / HB) * sB1 + (long)(z % HB) * sB2;
    float*       C  = Cg + (long)(z / HB) * sC1 + (long)(z % HB) * sC2;

    const int tid  = threadIdx.x;
    const int tx   = tid % TCOLS;
    const int ty   = tid / TCOLS;
    const int row0 = blockIdx.y * BM;
    const int col0 = blockIdx.x * BN;

    float acc[TM][TN];
#pragma unroll
    for (int i = 0; i < TM; i++)
#pragma unroll
        for (int j = 0; j < TN; j++) acc[i][j] = 0.f;

    for (int kt = 0; kt < K; kt += BK) {
        // Load A tile (BM x BK), float4 along k, store transposed As[k][m]
        for (int i = tid; i < BM * BK / 4; i += NT) {
            int k4 = (i % (BK / 4)) * 4;
            int m  = i / (BK / 4);
            float4 v = *reinterpret_cast<const float4*>(
                &A[(long)(row0 + m) * lda + kt + k4]);
            As[k4 + 0][m] = v.x; As[k4 + 1][m] = v.y;
            As[k4 + 2][m] = v.z; As[k4 + 3][m] = v.w;
        }
        if (TB) {
            // B logical [K,Nn] = Bm[n][k]; load float4 along k
            for (int i = tid; i < BN * BK / 4; i += NT) {
                int k4 = (i % (BK / 4)) * 4;
                int n  = i / (BK / 4);
                float4 v = *reinterpret_cast<const float4*>(
                    &Bp[(long)(col0 + n) * ldb + kt + k4]);
                Bs[k4 + 0][n] = v.x; Bs[k4 + 1][n] = v.y;
                Bs[k4 + 2][n] = v.z; Bs[k4 + 3][n] = v.w;
            }
        } else {
            for (int i = tid; i < BN * BK / 4; i += NT) {
                int n4 = (i % (BN / 4)) * 4;
                int k  = i / (BN / 4);
                float4 v = *reinterpret_cast<const float4*>(
                    &Bp[(long)(kt + k) * ldb + col0 + n4]);
                *reinterpret_cast<float4*>(&Bs[k][n4]) = v;
            }
        }
        __syncthreads();

#pragma unroll
        for (int k = 0; k < BK; k++) {
            float ra[TM], rb[TN];
#pragma unroll
            for (int i = 0; i < TM / 4; i++)
                *reinterpret_cast<float4*>(&ra[i * 4]) =
                    *reinterpret_cast<const float4*>(&As[k][ty * TM + i * 4]);
#pragma unroll
            for (int j = 0; j < TN / 4; j++)
                *reinterpret_cast<float4*>(&rb[j * 4]) =
                    *reinterpret_cast<const float4*>(&Bs[k][tx * TN + j * 4]);
#pragma unroll
            for (int i = 0; i < TM; i++)
#pragma unroll
                for (int j = 0; j < TN; j++) acc[i][j] += ra[i] * rb[j];
        }
        __syncthreads();
    }

    // Epilogue (vectorized stores)
#pragma unroll
    for (int i = 0; i < TM; i++) {
        long r = row0 + ty * TM + i;
#pragma unroll
        for (int j4 = 0; j4 < TN / 4; j4++) {
            int c = col0 + tx * TN + j4 * 4;
            float4 v;
            v.x = acc[i][j4 * 4 + 0] * alpha;
            v.y = acc[i][j4 * 4 + 1] * alpha;
            v.z = acc[i][j4 * 4 + 2] * alpha;
            v.w = acc[i][j4 * 4 + 3] * alpha;
            if (BIAS) {
                v.x += bias[c + 0]; v.y += bias[c + 1];
                v.z += bias[c + 2]; v.w += bias[c + 3];
            }
            *reinterpret_cast<float4*>(&C[r * ldc + c]) = v;
        }
    }
}

// ---------------------------------------------------------------------------
// Row softmax over the last dim (length KN). One block (256 thr) per row.
// ---------------------------------------------------------------------------
__global__ __launch_bounds__(256)
void softmax_kernel()
{
    float* p = g_attn + (long)blockIdx.x * KN;
    int t = threadIdx.x;
    float v0 = p[t], v1 = p[t + 256], v2 = p[t + 512], v3 = p[t + 768];

    float m = fmaxf(fmaxf(v0, v1), fmaxf(v2, v3));
#pragma unroll
    for (int o = 16; o; o >>= 1) m = fmaxf(m, __shfl_xor_sync(0xffffffffu, m, o));
    __shared__ float swm[8];
    if ((t & 31) == 0) swm[t >> 5] = m;
    __syncthreads();
    m = swm[0];
#pragma unroll
    for (int w = 1; w < 8; w++) m = fmaxf(m, swm[w]);

    v0 = __expf(v0 - m); v1 = __expf(v1 - m);
    v2 = __expf(v2 - m); v3 = __expf(v3 - m);

    float s = v0 + v1 + v2 + v3;
#pragma unroll
    for (int o = 16; o; o >>= 1) s += __shfl_xor_sync(0xffffffffu, s, o);
    __shared__ float sws[8];
    if ((t & 31) == 0) sws[t >> 5] = s;
    __syncthreads();
    s = sws[0];
#pragma unroll
    for (int w = 1; w < 8; w++) s += sws[w];

    float inv = 1.0f / s;
    p[t]       = v0 * inv; p[t + 256] = v1 * inv;
    p[t + 512] = v2 * inv; p[t + 768] = v3 * inv;
}

// ---------------------------------------------------------------------------
// Head-mix conv (no bias) + cross-head second-moment partials.
// One block per (b, n) row; threads stride over m.
// ---------------------------------------------------------------------------
__global__ __launch_bounds__(256)
void conv_mom_kernel(const float* __restrict__ cw)
{
    const int bidx = blockIdx.x;              // b*KN + n
    const int b = bidx >> 10;
    const int n = bidx & (KN - 1);
    const long hs = (long)KN * KN;
    const float* base  = g_attn + (long)b * KH * hs + (long)n * KN;
    float*       cbase = g_conv + (long)b * KH * hs + (long)n * KN;

    __shared__ float scw[64];
    if (threadIdx.x < 64) scw[threadIdx.x] = cw[threadIdx.x];
    __syncthreads();

    float s[36];
#pragma unroll
    for (int i = 0; i < 36; i++) s[i] = 0.f;

    for (int m = threadIdx.x; m < KN; m += 256) {
        float a[8];
#pragma unroll
        for (int h = 0; h < 8; h++) a[h] = base[h * hs + m];
        int p = 0;
#pragma unroll
        for (int h = 0; h < 8; h++)
#pragma unroll
            for (int h2 = h; h2 < 8; h2++) s[p++] += a[h] * a[h2];
#pragma unroll
        for (int g = 0; g < 8; g++) {
            float c = 0.f;
#pragma unroll
            for (int h = 0; h < 8; h++) c += scw[g * 8 + h] * a[h];
            cbase[g * hs + m] = c;
        }
    }

    __shared__ float red[8][36];
    int lane = threadIdx.x & 31, warp = threadIdx.x >> 5;
#pragma unroll
    for (int p = 0; p < 36; p++) {
        float v = s[p];
#pragma unroll
        for (int o = 16; o; o >>= 1) v += __shfl_xor_sync(0xffffffffu, v, o);
        if (lane == 0) red[warp][p] = v;
    }
    __syncthreads();
    if (threadIdx.x < 36) {
        float v = 0.f;
#pragma unroll
        for (int w = 0; w < 8; w++) v += red[w][threadIdx.x];
        g_part[(long)bidx * 36 + threadIdx.x] = v;
    }
}

// Deterministic reduction of moment partials -> g_S (means).
__global__ __launch_bounds__(256)
void reduce_kernel()
{
    const int p = blockIdx.x;   // 0..35
    float v = 0.f;
    for (int i = threadIdx.x; i < KB * KN; i += 256)
        v += g_part[(long)i * 36 + p];
    __shared__ float sm[256];
    sm[threadIdx.x] = v;
    __syncthreads();
    for (int o = 128; o; o >>= 1) {
        if (threadIdx.x < o) sm[threadIdx.x] += sm[threadIdx.x + o];
        __syncthreads();
    }
    if (threadIdx.x == 0) g_S[p] = sm[0] * (1.0f / 8388608.0f);  // / (B*N*N)
}

// Vsum[b,h,d] = sum_m V[b,h,m,d]. One block per (b,h), 256 threads.
__global__ __launch_bounds__(256)
void vsum_kernel()
{
    const int bh = blockIdx.x;
    const int t = threadIdx.x;
    const int d = t & 63;
    const int q = t >> 6;            // quarter of m-range
    const int b = bh >> 3, h = bh & 7;
    const float* p = g_qkv + (long)b * KN * KQ + 1024 + h * 64 + d;
    float s = 0.f;
    for (int m = q * 256; m < (q + 1) * 256; m++) s += p[(long)m * KQ];
    __shared__ float sm[256];
    sm[t] = s;
    __syncthreads();
    if (q == 0)
        g_vsum[bh * 64 + d] = sm[d] + sm[64 + d] + sm[128 + d] + sm[192 + d];
}

// BatchNorm coefficients from analytic mean + cross moments.
__global__ void stats_kernel(const float* __restrict__ cw,
                             const float* __restrict__ cb,
                             const float* __restrict__ gamma,
                             const float* __restrict__ beta)
{
    int g = threadIdx.x;
    if (g >= KH) return;
    float Sf[8][8];
    int p = 0;
    for (int h = 0; h < 8; h++)
        for (int h2 = h; h2 < 8; h2++) {
            float v = g_S[p++];
            Sf[h][h2] = v; Sf[h2][h] = v;
        }
    float meanC = 0.f;
    for (int h = 0; h < 8; h++) meanC += cw[g * 8 + h];
    meanC *= (1.0f / KN);                      // mean(A_h) = 1/N exactly
    float mean = meanC + cb[g];
    float e2 = cb[g] * cb[g] + 2.f * cb[g] * meanC;
    for (int h = 0; h < 8; h++)
        for (int h2 = 0; h2 < 8; h2++)
            e2 += cw[g * 8 + h] * cw[g * 8 + h2] * Sf[h][h2];
    float var = e2 - mean * mean;
    float s = gamma[g] * rsqrtf(var + 1e-5f);
    g_k1[g] = s;
    g_k0[g] = beta[g] - s * meanC;             // = beta + s*(cb - mean)
}

// Y[b,n,h*64+d] = k1[h]*U[b,h,n,d] + k0[h]*Vsum[b,h,d]
__global__ __launch_bounds__(256)
void assemble_kernel()
{
    int i = blockIdx.x * 256 + threadIdx.x;    // < KB*KN*KD = 4194304
    int c = i & 511;
    int h = c >> 6;
    int d = c & 63;
    int bn = i >> 9;
    int n = bn & (KN - 1);
    int b = bn >> 10;
    long ui = ((((long)b * KH + h) * KN) + n) * KDH + d;
    g_y[i] = g_k1[h] * g_u[ui] + g_k0[h] * g_vsum[(b * KH + h) * KDH + d];
}

// ---------------------------------------------------------------------------
// Launch
// ---------------------------------------------------------------------------
extern "C" void kernel_launch(void* const* d_in, const int* in_sizes, int n_in,
                              void* d_out, int out_size)
{
    const float* x      = (const float*)d_in[0];
    const float* w_qkv  = (const float*)d_in[1];
    const float* conv_w = (const float*)d_in[2];
    const float* conv_b = (const float*)d_in[3];
    const float* gamma  = (const float*)d_in[4];
    const float* beta   = (const float*)d_in[5];
    const float* w_out  = (const float*)d_in[6];
    const float* b_out  = (const float*)d_in[7];
    float* out = (float*)d_out;

    void *p_qkv, *p_attn, *p_conv, *p_u, *p_y;
    cudaGetSymbolAddress(&p_qkv,  g_qkv);
    cudaGetSymbolAddress(&p_attn, g_attn);
    cudaGetSymbolAddress(&p_conv, g_conv);
    cudaGetSymbolAddress(&p_u,    g_u);
    cudaGetSymbolAddress(&p_y,    g_y);

    // 1) QKV: [8192,1536] = x[8192,512] @ w_qkv[512,1536]
    gemm_kernel<128, 128, 16, 8, 8, false, false>
        <<<dim3(KQ / 128, KB * KN / 128, 1), 256>>>(
            x, w_qkv, (float*)p_qkv, nullptr,
            KB * KN, KQ, KD, KD, KQ, KQ,
            1, 0, 0, 0, 0, 0, 0, 1.0f);

    // 2) Logits per (b,h): A[n,m] = 0.125 * Q @ K^T  (Q,K strided views of qkv)
    gemm_kernel<128, 128, 16, 8, 8, true, false>
        <<<dim3(KN / 128, KN / 128, KB * KH), 256>>>(
            (const float*)p_qkv, (const float*)p_qkv + 512, (float*)p_attn, nullptr,
            KN, KN, KDH, KQ, KQ, KN,
            KH, (long)KN * KQ, 64, (long)KN * KQ, 64,
            (long)KH * KN * KN, (long)KN * KN, 0.125f);

    // 3) Row softmax
    softmax_kernel<<<KB * KH * KN, 256>>>();

    // 4) Conv head-mix + cross moments
    conv_mom_kernel<<<KB * KN, 256>>>(conv_w);

    // 5) Reduce moments; 6) Vsum; 7) BN coefficients
    reduce_kernel<<<36, 256>>>();
    vsum_kernel<<<KB * KH, 256>>>();
    stats_kernel<<<1, 32>>>(conv_w, conv_b, gamma, beta);

    // 8) U[b,g] = C[b,g] @ V[b,g]  (M=1024, N=64, K=1024)
    gemm_kernel<128, 64, 16, 8, 4, false, false>
        <<<dim3(1, KN / 128, KB * KH), 256>>>(
            (const float*)p_conv, (const float*)p_qkv + 1024, (float*)p_u, nullptr,
            KN, KDH, KN, KN, KQ, KDH,
            KH, (long)KH * KN * KN, (long)KN * KN, (long)KN * KQ, 64,
            (long)KN * KDH * KH, (long)KN * KDH, 1.0f);

    // 9) Assemble Y with deferred BN affine
    assemble_kernel<<<(KB * KN * KD) / 256, 256>>>();

    // 10) out = Y @ w_out + b_out
    gemm_kernel<128, 128, 16, 8, 8, false, true>
        <<<dim3(KD / 128, KB * KN / 128, 1), 256>>>(
            (const float*)p_y, w_out, out, b_out,
            KB * KN, KD, KD, KD, KD, KD,
            1, 0, 0, 0, 0, 0, 0, 1.0f);
}

// round 6
// speedup vs baseline: 1.1735x; 1.1735x over previous
#include <cuda_runtime.h>
#include <math.h>

// Problem constants
#define KB   8      // batch
#define KN   1024   // sequence length
#define KD   512    // model dim
#define KH   8      // heads
#define KDH  64     // dim per head
#define KQ   1536   // qkv columns

// ---------------------------------------------------------------------------
// Scratch (static __device__ arrays; allocation-free per harness rules)
// ---------------------------------------------------------------------------
__device__ __align__(16) float g_qkv [KB * KN * KQ];          // [B*N, 1536]
__device__ __align__(16) float g_attn[KB * KH * KN * KN];     // raw logits per (b,h)
__device__ __align__(16) float g_conv[KB * KH * KN * KN];     // C = conv-mix of softmax(A)
__device__ __align__(16) float g_u   [KB * KH * KN * KDH];    // U = C @ V
__device__ __align__(16) float g_y   [KB * KN * KD];          // assembled [b,n,(h d)]
__device__ __align__(16) float g_vsum[KB * KH * KDH];         // sum_m V[b,h,m,d]
__device__ __align__(16) float g_part[KB * KN * 36];          // per-(b,n) moment partials
__device__ __align__(16) float g_S   [36];                    // mean(A_h * A_h') upper-tri
__device__ float g_k0[KH];   // coefficient on Vsum
__device__ float g_k1[KH];   // coefficient on U

// ---------------------------------------------------------------------------
// Generic fp32 smem-tiled GEMM with packed fma.rn.f32x2 inner loop.
//   C[z] = alpha * A[z] (@ or @^T) B[z]  (+ bias)
// ---------------------------------------------------------------------------
template <int BM, int BN, int BK, int TM, int TN, bool TB, bool BIAS>
__global__ __launch_bounds__(256)
void gemm_kernel(const float* __restrict__ Ag, const float* __restrict__ Bg,
                 float* __restrict__ Cg, const float* __restrict__ bias,
                 int M, int Nn, int K, int lda, int ldb, int ldc,
                 int HB, long sA1, long sA2, long sB1, long sB2,
                 long sC1, long sC2, float alpha)
{
    constexpr int TCOLS = BN / TN;
    constexpr int NT    = (BM / TM) * (BN / TN);
    static_assert(NT == 256, "expect 256 threads");
    static_assert((TN & 3) == 0, "TN multiple of 4");

    __shared__ __align__(16) float As[BK][BM];
    __shared__ __align__(16) float Bs[BK][BN];

    const int z = blockIdx.z;
    const float* A  = Ag + (long)(z / HB) * sA1 + (long)(z % HB) * sA2;
    const float* Bp = Bg + (long)(z / HB) * sB1 + (long)(z % HB) * sB2;
    float*       C  = Cg + (long)(z / HB) * sC1 + (long)(z % HB) * sC2;

    const int tid  = threadIdx.x;
    const int tx   = tid % TCOLS;
    const int ty   = tid / TCOLS;
    const int row0 = blockIdx.y * BM;
    const int col0 = blockIdx.x * BN;

    // fp32x2 packed accumulators: lane .lo = col 2*j2, .hi = col 2*j2+1
    unsigned long long acc2[TM][TN / 2];
#pragma unroll
    for (int i = 0; i < TM; i++)
#pragma unroll
        for (int j = 0; j < TN / 2; j++) acc2[i][j] = 0ull;

    for (int kt = 0; kt < K; kt += BK) {
        // Load A tile (BM x BK), float4 along k, store transposed As[k][m]
        for (int i = tid; i < BM * BK / 4; i += NT) {
            int k4 = (i % (BK / 4)) * 4;
            int m  = i / (BK / 4);
            float4 v = *reinterpret_cast<const float4*>(
                &A[(long)(row0 + m) * lda + kt + k4]);
            As[k4 + 0][m] = v.x; As[k4 + 1][m] = v.y;
            As[k4 + 2][m] = v.z; As[k4 + 3][m] = v.w;
        }
        if (TB) {
            for (int i = tid; i < BN * BK / 4; i += NT) {
                int k4 = (i % (BK / 4)) * 4;
                int n  = i / (BK / 4);
                float4 v = *reinterpret_cast<const float4*>(
                    &Bp[(long)(col0 + n) * ldb + kt + k4]);
                Bs[k4 + 0][n] = v.x; Bs[k4 + 1][n] = v.y;
                Bs[k4 + 2][n] = v.z; Bs[k4 + 3][n] = v.w;
            }
        } else {
            for (int i = tid; i < BN * BK / 4; i += NT) {
                int n4 = (i % (BN / 4)) * 4;
                int k  = i / (BN / 4);
                float4 v = *reinterpret_cast<const float4*>(
                    &Bp[(long)(kt + k) * ldb + col0 + n4]);
                *reinterpret_cast<float4*>(&Bs[k][n4]) = v;
            }
        }
        __syncthreads();

#pragma unroll
        for (int k = 0; k < BK; k++) {
            float ra[TM];
            unsigned long long rb2[TN / 2];
#pragma unroll
            for (int i = 0; i < TM / 4; i++)
                *reinterpret_cast<float4*>(&ra[i * 4]) =
                    *reinterpret_cast<const float4*>(&As[k][ty * TM + i * 4]);
#pragma unroll
            for (int j4 = 0; j4 < TN / 4; j4++) {
                ulonglong2 t = *reinterpret_cast<const ulonglong2*>(
                    &Bs[k][tx * TN + j4 * 4]);
                rb2[j4 * 2 + 0] = t.x;
                rb2[j4 * 2 + 1] = t.y;
            }
#pragma unroll
            for (int i = 0; i < TM; i++) {
                unsigned long long a2;
                unsigned int au = __float_as_uint(ra[i]);
                asm("mov.b64 %0, {%1, %1};" : "=l"(a2) : "r"(au));
#pragma unroll
                for (int j = 0; j < TN / 2; j++) {
                    asm("fma.rn.f32x2 %0, %1, %2, %0;"
                        : "+l"(acc2[i][j]) : "l"(a2), "l"(rb2[j]));
                }
            }
        }
        __syncthreads();
    }

    // Epilogue (vectorized stores)
#pragma unroll
    for (int i = 0; i < TM; i++) {
        long r = row0 + ty * TM + i;
#pragma unroll
        for (int j4 = 0; j4 < TN / 4; j4++) {
            int c = col0 + tx * TN + j4 * 4;
            unsigned int u0, u1, u2, u3;
            asm("mov.b64 {%0, %1}, %2;" : "=r"(u0), "=r"(u1)
                : "l"(acc2[i][j4 * 2 + 0]));
            asm("mov.b64 {%0, %1}, %2;" : "=r"(u2), "=r"(u3)
                : "l"(acc2[i][j4 * 2 + 1]));
            float4 v;
            v.x = __uint_as_float(u0) * alpha;
            v.y = __uint_as_float(u1) * alpha;
            v.z = __uint_as_float(u2) * alpha;
            v.w = __uint_as_float(u3) * alpha;
            if (BIAS) {
                v.x += bias[c + 0]; v.y += bias[c + 1];
                v.z += bias[c + 2]; v.w += bias[c + 3];
            }
            *reinterpret_cast<float4*>(&C[r * ldc + c]) = v;
        }
    }
}

// ---------------------------------------------------------------------------
// Fused per-(b,n): softmax over m for all 8 heads + conv head-mix +
// cross-head second-moment partials. Logits read once, conv written once.
// ---------------------------------------------------------------------------
__global__ __launch_bounds__(256)
void smconv_kernel(const float* __restrict__ cw)
{
    __shared__ __align__(16) float sa[KH][KN];   // 32 KB: exp(logit - max)
    __shared__ float sinv[KH];                   // 1/rowsum per head
    __shared__ float scw[64];                    // cw[g][h] * sinv[h]
    __shared__ float red[8][36];

    const int bidx = blockIdx.x;              // b*KN + n
    const int b = bidx >> 10;
    const int n = bidx & (KN - 1);
    const long hs = (long)KN * KN;
    const float* base  = g_attn + (long)b * KH * hs + (long)n * KN;
    float*       cbase = g_conv + (long)b * KH * hs + (long)n * KN;

    const int tid = threadIdx.x;

    // Stage 8 head-rows into smem (float4)
    for (int i = tid; i < KH * KN / 4; i += 256) {
        int h  = i >> 8;          // KN/4 = 256 float4 per row
        int m4 = (i & 255) * 4;
        *reinterpret_cast<float4*>(&sa[h][m4]) =
            *reinterpret_cast<const float4*>(&base[(long)h * hs + m4]);
    }
    __syncthreads();

    // Per-warp softmax: warp w owns head w
    {
        const int w = tid >> 5, lane = tid & 31;
        float vmax = -1e30f;
        for (int i = lane; i < KN; i += 32) vmax = fmaxf(vmax, sa[w][i]);
#pragma unroll
        for (int o = 16; o; o >>= 1)
            vmax = fmaxf(vmax, __shfl_xor_sync(0xffffffffu, vmax, o));
        float s = 0.f;
        for (int i = lane; i < KN; i += 32) {
            float e = __expf(sa[w][i] - vmax);
            sa[w][i] = e;
            s += e;
        }
#pragma unroll
        for (int o = 16; o; o >>= 1) s += __shfl_xor_sync(0xffffffffu, s, o);
        if (lane == 0) sinv[w] = 1.0f / s;
    }
    __syncthreads();
    if (tid < 64) scw[tid] = cw[tid] * sinv[tid & 7];
    __syncthreads();

    // Each thread handles 4 consecutive m values
    const int m0 = tid * 4;
    float4 av[KH];
#pragma unroll
    for (int h = 0; h < KH; h++)
        av[h] = *reinterpret_cast<const float4*>(&sa[h][m0]);

    float s36[36];
#pragma unroll
    for (int p = 0; p < 36; p++) s36[p] = 0.f;
    float cv[KH][4];

#pragma unroll
    for (int e = 0; e < 4; e++) {
        float a8[KH];
#pragma unroll
        for (int h = 0; h < KH; h++)
            a8[h] = (e == 0) ? av[h].x : (e == 1) ? av[h].y
                   : (e == 2) ? av[h].z : av[h].w;
        int p = 0;
#pragma unroll
        for (int h = 0; h < KH; h++)
#pragma unroll
            for (int h2 = h; h2 < KH; h2++) s36[p++] += a8[h] * a8[h2];
#pragma unroll
        for (int g = 0; g < KH; g++) {
            float c = 0.f;
#pragma unroll
            for (int h = 0; h < KH; h++) c += scw[g * 8 + h] * a8[h];
            cv[g][e] = c;
        }
    }
#pragma unroll
    for (int g = 0; g < KH; g++) {
        float4 v; v.x = cv[g][0]; v.y = cv[g][1]; v.z = cv[g][2]; v.w = cv[g][3];
        *reinterpret_cast<float4*>(&cbase[(long)g * hs + m0]) = v;
    }

    // Block-reduce the 36 (raw e_h * e_h') partials, fold 1/sum factors
    const int lane = tid & 31, warp = tid >> 5;
#pragma unroll
    for (int p = 0; p < 36; p++) {
        float v = s36[p];
#pragma unroll
        for (int o = 16; o; o >>= 1) v += __shfl_xor_sync(0xffffffffu, v, o);
        if (lane == 0) red[warp][p] = v;
    }
    __syncthreads();
    if (tid < 36) {
        float v = 0.f;
#pragma unroll
        for (int w = 0; w < 8; w++) v += red[w][tid];
        // map flat upper-tri index -> (h, h2)
        int h = 0, rem = tid;
        while (rem >= KH - h) { rem -= KH - h; h++; }
        int h2 = h + rem;
        g_part[(long)bidx * 36 + tid] = v * sinv[h] * sinv[h2];
    }
}

// Deterministic reduction of moment partials -> g_S (means).
__global__ __launch_bounds__(256)
void reduce_kernel()
{
    const int p = blockIdx.x;   // 0..35
    float v = 0.f;
    for (int i = threadIdx.x; i < KB * KN; i += 256)
        v += g_part[(long)i * 36 + p];
    __shared__ float sm[256];
    sm[threadIdx.x] = v;
    __syncthreads();
    for (int o = 128; o; o >>= 1) {
        if (threadIdx.x < o) sm[threadIdx.x] += sm[threadIdx.x + o];
        __syncthreads();
    }
    if (threadIdx.x == 0) g_S[p] = sm[0] * (1.0f / 8388608.0f);  // / (B*N*N)
}

// Vsum[b,h,d] = sum_m V[b,h,m,d]. One block per (b,h), 256 threads.
__global__ __launch_bounds__(256)
void vsum_kernel()
{
    const int bh = blockIdx.x;
    const int t = threadIdx.x;
    const int d = t & 63;
    const int q = t >> 6;
    const int b = bh >> 3, h = bh & 7;
    const float* p = g_qkv + (long)b * KN * KQ + 1024 + h * 64 + d;
    float s = 0.f;
    for (int m = q * 256; m < (q + 1) * 256; m++) s += p[(long)m * KQ];
    __shared__ float sm[256];
    sm[t] = s;
    __syncthreads();
    if (q == 0)
        g_vsum[bh * 64 + d] = sm[d] + sm[64 + d] + sm[128 + d] + sm[192 + d];
}

// BatchNorm coefficients from analytic mean + cross moments.
__global__ void stats_kernel(const float* __restrict__ cw,
                             const float* __restrict__ cb,
                             const float* __restrict__ gamma,
                             const float* __restrict__ beta)
{
    int g = threadIdx.x;
    if (g >= KH) return;
    float Sf[8][8];
    int p = 0;
    for (int h = 0; h < 8; h++)
        for (int h2 = h; h2 < 8; h2++) {
            float v = g_S[p++];
            Sf[h][h2] = v; Sf[h2][h] = v;
        }
    float meanC = 0.f;
    for (int h = 0; h < 8; h++) meanC += cw[g * 8 + h];
    meanC *= (1.0f / KN);                      // mean(A_h) = 1/N exactly
    float mean = meanC + cb[g];
    float e2 = cb[g] * cb[g] + 2.f * cb[g] * meanC;
    for (int h = 0; h < 8; h++)
        for (int h2 = 0; h2 < 8; h2++)
            e2 += cw[g * 8 + h] * cw[g * 8 + h2] * Sf[h][h2];
    float var = e2 - mean * mean;
    float s = gamma[g] * rsqrtf(var + 1e-5f);
    g_k1[g] = s;
    g_k0[g] = beta[g] - s * meanC;             // = beta + s*(cb - mean)
}

// Y[b,n,h*64+d] = k1[h]*U[b,h,n,d] + k0[h]*Vsum[b,h,d]
__global__ __launch_bounds__(256)
void assemble_kernel()
{
    int i = blockIdx.x * 256 + threadIdx.x;    // < KB*KN*KD = 4194304
    int c = i & 511;
    int h = c >> 6;
    int d = c & 63;
    int bn = i >> 9;
    int n = bn & (KN - 1);
    int b = bn >> 10;
    long ui = ((((long)b * KH + h) * KN) + n) * KDH + d;
    g_y[i] = g_k1[h] * g_u[ui] + g_k0[h] * g_vsum[(b * KH + h) * KDH + d];
}

// ---------------------------------------------------------------------------
// Launch
// ---------------------------------------------------------------------------
extern "C" void kernel_launch(void* const* d_in, const int* in_sizes, int n_in,
                              void* d_out, int out_size)
{
    const float* x      = (const float*)d_in[0];
    const float* w_qkv  = (const float*)d_in[1];
    const float* conv_w = (const float*)d_in[2];
    const float* conv_b = (const float*)d_in[3];
    const float* gamma  = (const float*)d_in[4];
    const float* beta   = (const float*)d_in[5];
    const float* w_out  = (const float*)d_in[6];
    const float* b_out  = (const float*)d_in[7];
    float* out = (float*)d_out;

    void *p_qkv, *p_attn, *p_conv, *p_u, *p_y;
    cudaGetSymbolAddress(&p_qkv,  g_qkv);
    cudaGetSymbolAddress(&p_attn, g_attn);
    cudaGetSymbolAddress(&p_conv, g_conv);
    cudaGetSymbolAddress(&p_u,    g_u);
    cudaGetSymbolAddress(&p_y,    g_y);

    // 1) QKV: [8192,1536] = x[8192,512] @ w_qkv[512,1536]
    gemm_kernel<128, 128, 16, 8, 8, false, false>
        <<<dim3(KQ / 128, KB * KN / 128, 1), 256>>>(
            x, w_qkv, (float*)p_qkv, nullptr,
            KB * KN, KQ, KD, KD, KQ, KQ,
            1, 0, 0, 0, 0, 0, 0, 1.0f);

    // 2) Logits per (b,h): A[n,m] = 0.125 * Q @ K^T  (Q,K strided views of qkv)
    gemm_kernel<128, 128, 16, 8, 8, true, false>
        <<<dim3(KN / 128, KN / 128, KB * KH), 256>>>(
            (const float*)p_qkv, (const float*)p_qkv + 512, (float*)p_attn, nullptr,
            KN, KN, KDH, KQ, KQ, KN,
            KH, (long)KN * KQ, 64, (long)KN * KQ, 64,
            (long)KH * KN * KN, (long)KN * KN, 0.125f);

    // 3) Fused softmax + conv head-mix + cross moments
    smconv_kernel<<<KB * KN, 256>>>(conv_w);

    // 4) Reduce moments; 5) Vsum; 6) BN coefficients
    reduce_kernel<<<36, 256>>>();
    vsum_kernel<<<KB * KH, 256>>>();
    stats_kernel<<<1, 32>>>(conv_w, conv_b, gamma, beta);

    // 7) U[b,g] = C[b,g] @ V[b,g]  (M=1024, N=64, K=1024)
    gemm_kernel<128, 64, 16, 8, 4, false, false>
        <<<dim3(1, KN / 128, KB * KH), 256>>>(
            (const float*)p_conv, (const float*)p_qkv + 1024, (float*)p_u, nullptr,
            KN, KDH, KN, KN, KQ, KDH,
            KH, (long)KH * KN * KN, (long)KN * KN, (long)KN * KQ, 64,
            (long)KN * KDH * KH, (long)KN * KDH, 1.0f);

    // 8) Assemble Y with deferred BN affine
    assemble_kernel<<<(KB * KN * KD) / 256, 256>>>();

    // 9) out = Y @ w_out + b_out
    gemm_kernel<128, 128, 16, 8, 8, false, true>
        <<<dim3(KD / 128, KB * KN / 128, 1), 256>>>(
            (const float*)p_y, w_out, out, b_out,
            KB * KN, KD, KD, KD, KD, KD,
            1, 0, 0, 0, 0, 0, 0, 1.0f);
}

// round 8
// speedup vs baseline: 1.3375x; 1.1397x over previous
#include <cuda_runtime.h>
#include <cuda_bf16.h>
#include <math.h>
#include <cstdint>

// Problem constants
#define KB   8      // batch
#define KN   1024   // sequence length
#define KD   512    // model dim
#define KH   8      // heads
#define KDH  64     // dim per head
#define KQ   1536   // qkv columns

typedef __nv_bfloat16 bf16;
typedef __nv_bfloat162 bf162;

// Use tcgen05 only when an arch-specific (sm_103a/sm_100a) device pass compiles
#if defined(__CUDA_ARCH_FEAT_SM103_ALL) || defined(__CUDA_ARCH_FEAT_SM100_ALL)
#define USE_TC5 1
#else
#define USE_TC5 0
#endif

// ---------------------------------------------------------------------------
// Scratch (static __device__ arrays; allocation-free per harness rules)
// ---------------------------------------------------------------------------
__device__ __align__(16) bf16  g_xh [KB * KN * KD];           // x split hi
__device__ __align__(16) bf16  g_xl [KB * KN * KD];           // x split lo
__device__ __align__(16) bf16  g_wqh[KQ * KD];                // w_qkv^T hi
__device__ __align__(16) bf16  g_wql[KQ * KD];
__device__ __align__(16) bf16  g_woh[KD * KD];                // w_out^T hi
__device__ __align__(16) bf16  g_wol[KD * KD];
__device__ __align__(16) bf16  g_qkvh[KB * KN * KQ];          // qkv split hi
__device__ __align__(16) bf16  g_qkvl[KB * KN * KQ];
__device__ __align__(16) float g_attn[KB * KH * KN * KN];     // raw logits (fp32)
__device__ __align__(16) bf16  g_ch [KB * KH * KN * KN];      // C = conv-mix, hi
__device__ __align__(16) bf16  g_cl [KB * KH * KN * KN];      // C lo
__device__ __align__(16) bf16  g_vth[KB * KH * KDH * KN];     // V^T [bh, d, m] hi
__device__ __align__(16) bf16  g_vtl[KB * KH * KDH * KN];
__device__ __align__(16) float g_u  [KB * KH * KN * KDH];     // U = C @ V (fp32)
__device__ __align__(16) bf16  g_yh [KB * KN * KD];           // Y split hi
__device__ __align__(16) bf16  g_yl [KB * KN * KD];
__device__ __align__(16) float g_vsum[KB * KH * KDH];
__device__ __align__(16) float g_part[KB * KN * 36];
__device__ __align__(16) float g_S  [36];
__device__ float g_k0[KH];
__device__ float g_k1[KH];

// ---------------------------------------------------------------------------
// Helpers
// ---------------------------------------------------------------------------
__device__ __forceinline__ uint32_t smem_u32(const void* p) {
    uint32_t a;
    asm("{ .reg .u64 t; cvta.to.shared.u64 t, %1; cvt.u32.u64 %0, t; }"
        : "=r"(a) : "l"(p));
    return a;
}
#define SW128(x) ((x) ^ (((x) >> 3) & 0x70))

__device__ __forceinline__ void split_bf(float v, bf16& h, bf16& l) {
    h = __float2bfloat16(v);
    l = __float2bfloat16(v - __bfloat162float(h));
}

// ldmatrix x4 (b16)
__device__ __forceinline__ void ldsm4(uint32_t addr, uint32_t* r) {
    asm volatile("ldmatrix.sync.aligned.m8n8.x4.shared.b16 {%0,%1,%2,%3}, [%4];"
                 : "=r"(r[0]), "=r"(r[1]), "=r"(r[2]), "=r"(r[3]) : "r"(addr));
}
// mma m16n8k16 bf16 -> f32 accumulate
__device__ __forceinline__ void mma16816(float* c, const uint32_t* a,
                                         uint32_t b0, uint32_t b1) {
    asm volatile(
        "mma.sync.aligned.m16n8k16.row.col.f32.bf16.bf16.f32 "
        "{%0,%1,%2,%3}, {%4,%5,%6,%7}, {%8,%9}, {%0,%1,%2,%3};"
        : "+f"(c[0]), "+f"(c[1]), "+f"(c[2]), "+f"(c[3])
        : "r"(a[0]), "r"(a[1]), "r"(a[2]), "r"(a[3]), "r"(b0), "r"(b1));
}

#if USE_TC5
__device__ __forceinline__ uint32_t elect1() {
    uint32_t p;
    asm volatile("{\n\t.reg .pred p;\n\telect.sync _|p, 0xFFFFFFFF;\n\t"
                 "selp.b32 %0, 1, 0, p;\n\t}" : "=r"(p));
    return p;
}
static constexpr unsigned long long SMEM_DESC_BASE_SW128 =
    (2ull << 61) | (1ull << 46) | (64ull << 32) | (1ull << 16);
__device__ __forceinline__ unsigned long long mkdesc(uint32_t a) {
    return SMEM_DESC_BASE_SW128 | ((unsigned long long)(a >> 4) & 0x3FFF);
}
#define TCGEN05_ALLOC(sa, n)                                                   \
    asm volatile("tcgen05.alloc.cta_group::1.sync.aligned.shared::cta.b32 "    \
                 "[%0], %1;" :: "r"((uint32_t)(sa)), "r"((uint32_t)(n))        \
                 : "memory")
#define TCGEN05_DEALLOC(t, n)                                                  \
    asm volatile("tcgen05.dealloc.cta_group::1.sync.aligned.b32 %0, %1;"       \
                 :: "r"(t), "r"((uint32_t)(n)))
#define TCGEN05_COMMIT(m)                                                      \
    asm volatile("tcgen05.commit.cta_group::1.mbarrier::arrive::one."          \
                 "shared::cluster.b64 [%0];" :: "r"((uint32_t)(m)) : "memory")
#define MBARRIER_INIT(m, c)                                                    \
    asm volatile("mbarrier.init.shared.b64 [%0], %1;"                          \
                 :: "r"((uint32_t)(m)), "r"((uint32_t)(c)) : "memory")
#define MBARRIER_INVAL(m)                                                      \
    asm volatile("mbarrier.inval.shared.b64 [%0];" :: "r"((uint32_t)(m))       \
                 : "memory")
#define TCGEN05_FENCE_AFTER()                                                  \
    asm volatile("tcgen05.fence::after_thread_sync;" ::: "memory")
#define TCGEN05_FENCE_BEFORE()                                                 \
    asm volatile("tcgen05.fence::before_thread_sync;" ::: "memory")
#define TCGEN05_WAIT_LD()                                                      \
    asm volatile("tcgen05.wait::ld.sync.aligned;" ::: "memory")
#define FENCE_PROXY_ASYNC()                                                    \
    asm volatile("fence.proxy.async.shared::cta;" ::: "memory")
#define MBARRIER_WAIT_PARITY(mb, ph) do {                                      \
    uint32_t _mbar = (uint32_t)(mb);                                           \
    uint32_t _parity = (uint32_t)(ph);                                         \
    uint32_t _done;                                                            \
    asm volatile(                                                              \
        "{\n\t.reg .pred p;\n\t"                                               \
        "mbarrier.try_wait.parity.acquire.cta.shared::cta.b64 p, [%1], %2;\n\t"\
        "selp.b32 %0, 1, 0, p;\n\t}"                                           \
        : "=r"(_done) : "r"(_mbar), "r"(_parity) : "memory");                  \
    if (!_done) {                                                              \
        asm volatile(                                                          \
            "{\n\t.reg .pred P1;\n\t"                                          \
            "WAIT_LOOP_%=:\n\t"                                                \
            "mbarrier.try_wait.parity.acquire.cta.shared::cta.b64 P1, [%0], "  \
            "%1, 0x989680;\n\t"                                                \
            "@P1 bra.uni WAIT_DONE_%=;\n\t"                                    \
            "bra.uni WAIT_LOOP_%=;\n\t"                                        \
            "WAIT_DONE_%=:\n\t}"                                               \
            :: "r"(_mbar), "r"(_parity) : "memory");                           \
    }                                                                          \
} while (0)
__device__ __forceinline__ void mma_ss(uint32_t d, unsigned long long ad,
                                       unsigned long long bd, uint32_t idesc,
                                       uint32_t en)
{
    asm volatile(
        "{\n\t.reg .pred p;\n\tsetp.ne.u32 p, %5, 0;\n\t"
        "tcgen05.mma.cta_group::1.kind::f16 [%0], %1, %2, %3, "
        "{%4, %4, %4, %4}, p;\n\t}"
        :: "r"(d), "l"(ad), "l"(bd), "r"(idesc), "r"(0u), "r"(en)
        : "memory");
}
#define LDTM_X32(r, tmem_addr)                                                 \
    asm volatile(                                                              \
        "tcgen05.ld.sync.aligned.32x32b.x32.b32 "                              \
        "{%0, %1, %2, %3, %4, %5, %6, %7, "                                    \
        " %8, %9, %10, %11, %12, %13, %14, %15, "                              \
        " %16, %17, %18, %19, %20, %21, %22, %23, "                            \
        " %24, %25, %26, %27, %28, %29, %30, %31}, [%32];"                     \
        : "=r"((r)[0]),  "=r"((r)[1]),  "=r"((r)[2]),  "=r"((r)[3]),           \
          "=r"((r)[4]),  "=r"((r)[5]),  "=r"((r)[6]),  "=r"((r)[7]),           \
          "=r"((r)[8]),  "=r"((r)[9]),  "=r"((r)[10]), "=r"((r)[11]),          \
          "=r"((r)[12]), "=r"((r)[13]), "=r"((r)[14]), "=r"((r)[15]),          \
          "=r"((r)[16]), "=r"((r)[17]), "=r"((r)[18]), "=r"((r)[19]),          \
          "=r"((r)[20]), "=r"((r)[21]), "=r"((r)[22]), "=r"((r)[23]),          \
          "=r"((r)[24]), "=r"((r)[25]), "=r"((r)[26]), "=r"((r)[27]),          \
          "=r"((r)[28]), "=r"((r)[29]), "=r"((r)[30]), "=r"((r)[31])           \
        : "r"(tmem_addr))
#endif  // USE_TC5

// ---------------------------------------------------------------------------
// bf16x2-split GEMM: D[128 x BN] = alpha * A @ B^T (+bias)
//   A rows K-major (bf16 hi/lo), B rows K-major (i.e. B[n][k]). K mult of 64.
//   MODE 0: fp32 out *alpha; 1: fp32 *alpha + bias; 2: bf16 hi/lo pair out.
//   Path: tcgen05 when arch-specific pass compiles, else mma.sync fallback.
// ---------------------------------------------------------------------------
template <int BN, int MODE>
__global__ __launch_bounds__(256)
void tc_gemm(const bf16* __restrict__ Ah, const bf16* __restrict__ Al,
             const bf16* __restrict__ Bh, const bf16* __restrict__ Bl,
             float* __restrict__ Cf, bf16* __restrict__ Ch,
             bf16* __restrict__ Cl, const float* __restrict__ bias,
             int K, int lda, int ldb, int ldc,
             int HB, long sA1, long sA2, long sB1, long sB2,
             long sC1, long sC2, float alpha)
{
    extern __shared__ __align__(1024) char smem[];
    constexpr int OFF_AH = 1024;
    constexpr int OFF_AL = OFF_AH + 16384;
    constexpr int OFF_BH = OFF_AL + 16384;
    constexpr int OFF_BL = OFF_BH + BN * 128;

    const uint32_t sb = smem_u32(smem);
    const int tid = threadIdx.x, wid = tid >> 5, lane = tid & 31;
    const int z = blockIdx.z;
    const long zq = z / HB, zr = z % HB;
    const bf16* pAh = Ah + zq * sA1 + zr * sA2;
    const bf16* pAl = Al + zq * sA1 + zr * sA2;
    const bf16* pBh = Bh + zq * sB1 + zr * sB2;
    const bf16* pBl = Bl + zq * sB1 + zr * sB2;
    const int row0 = blockIdx.y * 128;
    const int col0 = blockIdx.x * BN;
    const int nch = K >> 6;

#if USE_TC5
    // ---------------- tcgen05 path ----------------
    if (wid == 0) TCGEN05_ALLOC(sb + 0, 128);
    if (tid == 0) MBARRIER_INIT(sb + 8, 1);
    __syncthreads();
    uint32_t tb;
    asm volatile("ld.shared.b32 %0, [%1];" : "=r"(tb) : "r"(sb + 0));

    const uint32_t idesc =
        (1u << 4) | (1u << 7) | (1u << 10) | ((BN / 8) << 17) | (8u << 24);

    for (int ch = 0; ch < nch; ch++) {
        const int kt = ch << 6;
        for (int i = tid; i < 128 * 8; i += 256) {
            int r = i >> 3, c = (i & 7) * 16;
            uint32_t so = SW128(r * 128 + c);
            long gi = (long)(row0 + r) * lda + kt + (c >> 1);
            *(uint4*)(smem + OFF_AH + so) = *(const uint4*)(pAh + gi);
            *(uint4*)(smem + OFF_AL + so) = *(const uint4*)(pAl + gi);
        }
        for (int i = tid; i < BN * 8; i += 256) {
            int r = i >> 3, c = (i & 7) * 16;
            uint32_t so = SW128(r * 128 + c);
            long gi = (long)(col0 + r) * ldb + kt + (c >> 1);
            *(uint4*)(smem + OFF_BH + so) = *(const uint4*)(pBh + gi);
            *(uint4*)(smem + OFF_BL + so) = *(const uint4*)(pBl + gi);
        }
        __syncthreads();
        FENCE_PROXY_ASYNC();

        if (wid == 0 && elect1()) {
            unsigned long long dah = mkdesc(sb + OFF_AH);
            unsigned long long dal = mkdesc(sb + OFF_AL);
            unsigned long long dbh = mkdesc(sb + OFF_BH);
            unsigned long long dbl = mkdesc(sb + OFF_BL);
#pragma unroll
            for (int k = 0; k < 4; k++)
                mma_ss(tb, dah + k * 2, dbh + k * 2, idesc, (ch | k) != 0);
#pragma unroll
            for (int k = 0; k < 4; k++)
                mma_ss(tb, dah + k * 2, dbl + k * 2, idesc, 1);
#pragma unroll
            for (int k = 0; k < 4; k++)
                mma_ss(tb, dal + k * 2, dbh + k * 2, idesc, 1);
            TCGEN05_COMMIT(sb + 8);
        }
        MBARRIER_WAIT_PARITY(sb + 8, ch & 1);
        __syncthreads();
    }

    TCGEN05_FENCE_AFTER();

    // Epilogue: warp w -> rows (w&3)*32+lane, cols (w>>2)*(BN/2)..
    constexpr int HC = BN / 2;
    uint32_t dr[HC];
    const int cbase = (wid >> 2) * HC;
#pragma unroll
    for (int b0 = 0; b0 < HC; b0 += 32) LDTM_X32(dr + b0, tb + cbase + b0);
    TCGEN05_WAIT_LD();
    TCGEN05_FENCE_BEFORE();

    const long r = row0 + (wid & 3) * 32 + lane;
    if (MODE == 0 || MODE == 1) {
        float* pC = Cf + zq * sC1 + zr * sC2;
#pragma unroll
        for (int j = 0; j < HC; j += 4) {
            int c = col0 + cbase + j;
            float4 v;
            v.x = __uint_as_float(dr[j + 0]) * alpha;
            v.y = __uint_as_float(dr[j + 1]) * alpha;
            v.z = __uint_as_float(dr[j + 2]) * alpha;
            v.w = __uint_as_float(dr[j + 3]) * alpha;
            if (MODE == 1) {
                v.x += bias[c + 0]; v.y += bias[c + 1];
                v.z += bias[c + 2]; v.w += bias[c + 3];
            }
            *(float4*)&pC[r * ldc + c] = v;
        }
    } else {
        bf16* pH = Ch + zq * sC1 + zr * sC2;
        bf16* pL = Cl + zq * sC1 + zr * sC2;
#pragma unroll
        for (int j = 0; j < HC; j += 2) {
            int c = col0 + cbase + j;
            float v0 = __uint_as_float(dr[j + 0]) * alpha;
            float v1 = __uint_as_float(dr[j + 1]) * alpha;
            bf16 h0, l0, h1, l1;
            split_bf(v0, h0, l0);
            split_bf(v1, h1, l1);
            bf162 hh; hh.x = h0; hh.y = h1;
            bf162 ll; ll.x = l0; ll.y = l1;
            *(bf162*)&pH[r * ldc + c] = hh;
            *(bf162*)&pL[r * ldc + c] = ll;
        }
    }

    __syncthreads();
    if (tid == 0) MBARRIER_INVAL(sb + 8);
    __syncthreads();
    if (wid == 0) TCGEN05_DEALLOC(tb, 128);

#else
    // ---------------- mma.sync fallback path ----------------
    constexpr int WNT = BN / 2;          // warp n-tile width (64 or 32)
    constexpr int NI  = WNT / 8;         // n 16x8 tiles per warp
    constexpr int NPT = WNT / 16;        // ldmatrix.x4 pairs per warp
    const int wr = wid & 3;              // row group (32 rows)
    const int wc = wid >> 2;             // col group

    float acc[2][NI][4];
#pragma unroll
    for (int mi = 0; mi < 2; mi++)
#pragma unroll
        for (int ni = 0; ni < NI; ni++)
#pragma unroll
            for (int e = 0; e < 4; e++) acc[mi][ni][e] = 0.f;

    const int arow = lane & 15;
    const int akb  = (lane >> 4) << 4;
    const int brow = ((lane >> 4) << 3) + (lane & 7);
    const int bkb  = ((lane >> 3) & 1) << 4;

    for (int ch = 0; ch < nch; ch++) {
        const int kt = ch << 6;
        for (int i = tid; i < 128 * 8; i += 256) {
            int r = i >> 3, c = (i & 7) * 16;
            uint32_t so = SW128(r * 128 + c);
            long gi = (long)(row0 + r) * lda + kt + (c >> 1);
            *(uint4*)(smem + OFF_AH + so) = *(const uint4*)(pAh + gi);
            *(uint4*)(smem + OFF_AL + so) = *(const uint4*)(pAl + gi);
        }
        for (int i = tid; i < BN * 8; i += 256) {
            int r = i >> 3, c = (i & 7) * 16;
            uint32_t so = SW128(r * 128 + c);
            long gi = (long)(col0 + r) * ldb + kt + (c >> 1);
            *(uint4*)(smem + OFF_BH + so) = *(const uint4*)(pBh + gi);
            *(uint4*)(smem + OFF_BL + so) = *(const uint4*)(pBl + gi);
        }
        __syncthreads();

#pragma unroll
        for (int k16 = 0; k16 < 4; k16++) {
            uint32_t ah[2][4], al2[2][4];
#pragma unroll
            for (int mi = 0; mi < 2; mi++) {
                uint32_t off = SW128((wr * 32 + mi * 16 + arow) * 128 +
                                     k16 * 32 + akb);
                ldsm4(sb + OFF_AH + off, ah[mi]);
                ldsm4(sb + OFF_AL + off, al2[mi]);
            }
            uint32_t bh2[NPT][4], bl2[NPT][4];
#pragma unroll
            for (int np = 0; np < NPT; np++) {
                uint32_t off = SW128((wc * WNT + np * 16 + brow) * 128 +
                                     k16 * 32 + bkb);
                ldsm4(sb + OFF_BH + off, bh2[np]);
                ldsm4(sb + OFF_BL + off, bl2[np]);
            }
#pragma unroll
            for (int mi = 0; mi < 2; mi++)
#pragma unroll
                for (int np = 0; np < NPT; np++) {
                    mma16816(acc[mi][2 * np], ah[mi], bh2[np][0], bh2[np][1]);
                    mma16816(acc[mi][2 * np], ah[mi], bl2[np][0], bl2[np][1]);
                    mma16816(acc[mi][2 * np], al2[mi], bh2[np][0], bh2[np][1]);
                    mma16816(acc[mi][2 * np + 1], ah[mi], bh2[np][2], bh2[np][3]);
                    mma16816(acc[mi][2 * np + 1], ah[mi], bl2[np][2], bl2[np][3]);
                    mma16816(acc[mi][2 * np + 1], al2[mi], bh2[np][2], bh2[np][3]);
                }
        }
        __syncthreads();
    }

    // Epilogue: c0=(m=qrow,n=qcol), c1=(m,n+1), c2=(m+8,n), c3=(m+8,n+1)
    const int qrow = lane >> 2;
    const int qcol = (lane & 3) * 2;
#pragma unroll
    for (int mi = 0; mi < 2; mi++) {
        const long rb = row0 + wr * 32 + mi * 16 + qrow;
#pragma unroll
        for (int ni = 0; ni < NI; ni++) {
            const int c = col0 + wc * WNT + ni * 8 + qcol;
            float v0 = acc[mi][ni][0] * alpha;
            float v1 = acc[mi][ni][1] * alpha;
            float v2 = acc[mi][ni][2] * alpha;
            float v3 = acc[mi][ni][3] * alpha;
            if (MODE == 1) {
                v0 += bias[c]; v1 += bias[c + 1];
                v2 += bias[c]; v3 += bias[c + 1];
            }
            if (MODE == 0 || MODE == 1) {
                float* pC = Cf + zq * sC1 + zr * sC2;
                float2 w0; w0.x = v0; w0.y = v1;
                float2 w1; w1.x = v2; w1.y = v3;
                *(float2*)&pC[rb * ldc + c] = w0;
                *(float2*)&pC[(rb + 8) * ldc + c] = w1;
            } else {
                bf16* pH = Ch + zq * sC1 + zr * sC2;
                bf16* pL = Cl + zq * sC1 + zr * sC2;
                bf16 h0, l0, h1, l1, h2, l2, h3, l3;
                split_bf(v0, h0, l0); split_bf(v1, h1, l1);
                split_bf(v2, h2, l2); split_bf(v3, h3, l3);
                bf162 ha; ha.x = h0; ha.y = h1;
                bf162 hb; hb.x = h2; hb.y = h3;
                bf162 la; la.x = l0; la.y = l1;
                bf162 lb; lb.x = l2; lb.y = l3;
                *(bf162*)&pH[rb * ldc + c] = ha;
                *(bf162*)&pL[rb * ldc + c] = la;
                *(bf162*)&pH[(rb + 8) * ldc + c] = hb;
                *(bf162*)&pL[(rb + 8) * ldc + c] = lb;
            }
        }
    }
#endif
}

// ---------------------------------------------------------------------------
// Conversion / transpose kernels
// ---------------------------------------------------------------------------
__global__ __launch_bounds__(256)
void splitf_kernel(const float* __restrict__ in, bf16* __restrict__ oh,
                   bf16* __restrict__ ol, int n)
{
    int i = blockIdx.x * 256 + threadIdx.x;
    if (i < n) {
        bf16 h, l;
        split_bf(in[i], h, l);
        oh[i] = h; ol[i] = l;
    }
}

// out[c, r] = split(in[r, c]); in is R x C row-major. Grid (C/32, R/32), blk (32,8)
__global__ __launch_bounds__(256)
void tsplit_kernel(const float* __restrict__ in, bf16* __restrict__ oh,
                   bf16* __restrict__ ol, int R, int C)
{
    __shared__ float t[32][33];
    int c0 = blockIdx.x * 32, r0 = blockIdx.y * 32;
    for (int i = threadIdx.y; i < 32; i += 8)
        t[i][threadIdx.x] = in[(long)(r0 + i) * C + c0 + threadIdx.x];
    __syncthreads();
    for (int i = threadIdx.y; i < 32; i += 8) {
        float v = t[threadIdx.x][i];
        long o = (long)(c0 + i) * R + r0 + threadIdx.x;
        bf16 h, l;
        split_bf(v, h, l);
        oh[o] = h; ol[o] = l;
    }
}

// V^T: g_vt[bh, d, m] = qkv pair [b, m, 1024 + h*64 + d].
__global__ __launch_bounds__(256)
void vtrans_kernel()
{
    __shared__ bf16 th[32][40], tl[32][40];
    const int bh = blockIdx.z;
    const int b = bh >> 3, h = bh & 7;
    const int m0 = blockIdx.x * 32, d0 = blockIdx.y * 32;
    const bf16* ih = g_qkvh + (long)b * KN * KQ + 1024 + h * 64 + d0;
    const bf16* il = g_qkvl + (long)b * KN * KQ + 1024 + h * 64 + d0;
    for (int i = threadIdx.y; i < 32; i += 8) {
        th[i][threadIdx.x] = ih[(long)(m0 + i) * KQ + threadIdx.x];
        tl[i][threadIdx.x] = il[(long)(m0 + i) * KQ + threadIdx.x];
    }
    __syncthreads();
    bf16* oh = g_vth + ((long)bh * KDH + d0) * KN + m0;
    bf16* ol = g_vtl + ((long)bh * KDH + d0) * KN + m0;
    for (int i = threadIdx.y; i < 32; i += 8) {
        oh[(long)i * KN + threadIdx.x] = th[threadIdx.x][i];
        ol[(long)i * KN + threadIdx.x] = tl[threadIdx.x][i];
    }
}

// ---------------------------------------------------------------------------
// Fused per-(b,n): softmax (8 heads) + conv head-mix (-> bf16 pairs) + moments
// ---------------------------------------------------------------------------
__global__ __launch_bounds__(256)
void smconv_kernel(const float* __restrict__ cw)
{
    __shared__ __align__(16) float sa[KH][KN];
    __shared__ float sinv[KH];
    __shared__ float scw[64];
    __shared__ float red[8][36];

    const int bidx = blockIdx.x;
    const int b = bidx >> 10;
    const int n = bidx & (KN - 1);
    const long hs = (long)KN * KN;
    const float* base = g_attn + (long)b * KH * hs + (long)n * KN;
    bf16* chb = g_ch + (long)b * KH * hs + (long)n * KN;
    bf16* clb = g_cl + (long)b * KH * hs + (long)n * KN;

    const int tid = threadIdx.x;

    for (int i = tid; i < KH * KN / 4; i += 256) {
        int h = i >> 8;
        int m4 = (i & 255) * 4;
        *reinterpret_cast<float4*>(&sa[h][m4]) =
            *reinterpret_cast<const float4*>(&base[(long)h * hs + m4]);
    }
    __syncthreads();

    {
        const int w = tid >> 5, lane = tid & 31;
        float vmax = -1e30f;
        for (int i = lane; i < KN; i += 32) vmax = fmaxf(vmax, sa[w][i]);
#pragma unroll
        for (int o = 16; o; o >>= 1)
            vmax = fmaxf(vmax, __shfl_xor_sync(0xffffffffu, vmax, o));
        float s = 0.f;
        for (int i = lane; i < KN; i += 32) {
            float e = __expf(sa[w][i] - vmax);
            sa[w][i] = e;
            s += e;
        }
#pragma unroll
        for (int o = 16; o; o >>= 1) s += __shfl_xor_sync(0xffffffffu, s, o);
        if (lane == 0) sinv[w] = 1.0f / s;
    }
    __syncthreads();
    if (tid < 64) scw[tid] = cw[tid] * sinv[tid & 7];
    __syncthreads();

    const int m0 = tid * 4;
    float4 av[KH];
#pragma unroll
    for (int h = 0; h < KH; h++)
        av[h] = *reinterpret_cast<const float4*>(&sa[h][m0]);

    float s36[36];
#pragma unroll
    for (int p = 0; p < 36; p++) s36[p] = 0.f;
    float cv[KH][4];

#pragma unroll
    for (int e = 0; e < 4; e++) {
        float a8[KH];
#pragma unroll
        for (int h = 0; h < KH; h++)
            a8[h] = (e == 0) ? av[h].x : (e == 1) ? av[h].y
                   : (e == 2) ? av[h].z : av[h].w;
        int p = 0;
#pragma unroll
        for (int h = 0; h < KH; h++)
#pragma unroll
            for (int h2 = h; h2 < KH; h2++) s36[p++] += a8[h] * a8[h2];
#pragma unroll
        for (int g = 0; g < KH; g++) {
            float c = 0.f;
#pragma unroll
            for (int h = 0; h < KH; h++) c += scw[g * 8 + h] * a8[h];
            cv[g][e] = c;
        }
    }
#pragma unroll
    for (int g = 0; g < KH; g++) {
        bf16 h0, l0, h1, l1, h2, l2, h3, l3;
        split_bf(cv[g][0], h0, l0);
        split_bf(cv[g][1], h1, l1);
        split_bf(cv[g][2], h2, l2);
        split_bf(cv[g][3], h3, l3);
        bf162 ha; ha.x = h0; ha.y = h1;
        bf162 hb; hb.x = h2; hb.y = h3;
        bf162 la; la.x = l0; la.y = l1;
        bf162 lb; lb.x = l2; lb.y = l3;
        *(bf162*)&chb[(long)g * hs + m0]     = ha;
        *(bf162*)&chb[(long)g * hs + m0 + 2] = hb;
        *(bf162*)&clb[(long)g * hs + m0]     = la;
        *(bf162*)&clb[(long)g * hs + m0 + 2] = lb;
    }

    const int lane = tid & 31, warp = tid >> 5;
#pragma unroll
    for (int p = 0; p < 36; p++) {
        float v = s36[p];
#pragma unroll
        for (int o = 16; o; o >>= 1) v += __shfl_xor_sync(0xffffffffu, v, o);
        if (lane == 0) red[warp][p] = v;
    }
    __syncthreads();
    if (tid < 36) {
        float v = 0.f;
#pragma unroll
        for (int w = 0; w < 8; w++) v += red[w][tid];
        int h = 0, rem = tid;
        while (rem >= KH - h) { rem -= KH - h; h++; }
        int h2 = h + rem;
        g_part[(long)bidx * 36 + tid] = v * sinv[h] * sinv[h2];
    }
}

// Deterministic reduction of moment partials -> g_S (means).
__global__ __launch_bounds__(256)
void reduce_kernel()
{
    const int p = blockIdx.x;
    float v = 0.f;
    for (int i = threadIdx.x; i < KB * KN; i += 256)
        v += g_part[(long)i * 36 + p];
    __shared__ float sm[256];
    sm[threadIdx.x] = v;
    __syncthreads();
    for (int o = 128; o; o >>= 1) {
        if (threadIdx.x < o) sm[threadIdx.x] += sm[threadIdx.x + o];
        __syncthreads();
    }
    if (threadIdx.x == 0) g_S[p] = sm[0] * (1.0f / 8388608.0f);
}

// Vsum[b,h,d] = sum_m V[b,h,m,d] (from bf16 pairs).
__global__ __launch_bounds__(256)
void vsum_kernel()
{
    const int bh = blockIdx.x;
    const int t = threadIdx.x;
    const int d = t & 63;
    const int q = t >> 6;
    const int b = bh >> 3, h = bh & 7;
    const bf16* ph = g_qkvh + (long)b * KN * KQ + 1024 + h * 64 + d;
    const bf16* pl = g_qkvl + (long)b * KN * KQ + 1024 + h * 64 + d;
    float s = 0.f;
    for (int m = q * 256; m < (q + 1) * 256; m++)
        s += __bfloat162float(ph[(long)m * KQ]) + __bfloat162float(pl[(long)m * KQ]);
    __shared__ float sm[256];
    sm[t] = s;
    __syncthreads();
    if (q == 0)
        g_vsum[bh * 64 + d] = sm[d] + sm[64 + d] + sm[128 + d] + sm[192 + d];
}

// BatchNorm coefficients from analytic mean + cross moments.
__global__ void stats_kernel(const float* __restrict__ cw,
                             const float* __restrict__ cb,
                             const float* __restrict__ gamma,
                             const float* __restrict__ beta)
{
    int g = threadIdx.x;
    if (g >= KH) return;
    float Sf[8][8];
    int p = 0;
    for (int h = 0; h < 8; h++)
        for (int h2 = h; h2 < 8; h2++) {
            float v = g_S[p++];
            Sf[h][h2] = v; Sf[h2][h] = v;
        }
    float meanC = 0.f;
    for (int h = 0; h < 8; h++) meanC += cw[g * 8 + h];
    meanC *= (1.0f / KN);
    float mean = meanC + cb[g];
    float e2 = cb[g] * cb[g] + 2.f * cb[g] * meanC;
    for (int h = 0; h < 8; h++)
        for (int h2 = 0; h2 < 8; h2++)
            e2 += cw[g * 8 + h] * cw[g * 8 + h2] * Sf[h][h2];
    float var = e2 - mean * mean;
    float s = gamma[g] * rsqrtf(var + 1e-5f);
    g_k1[g] = s;
    g_k0[g] = beta[g] - s * meanC;
}

// Y[b,n,h*64+d] = k1[h]*U[b,h,n,d] + k0[h]*Vsum[b,h,d], split to bf16 pair
__global__ __launch_bounds__(256)
void assemble_kernel()
{
    int i = blockIdx.x * 256 + threadIdx.x;
    int c = i & 511;
    int h = c >> 6;
    int d = c & 63;
    int bn = i >> 9;
    int n = bn & (KN - 1);
    int b = bn >> 10;
    long ui = ((((long)b * KH + h) * KN) + n) * KDH + d;
    float v = g_k1[h] * g_u[ui] + g_k0[h] * g_vsum[(b * KH + h) * KDH + d];
    bf16 hh, ll;
    split_bf(v, hh, ll);
    g_yh[i] = hh; g_yl[i] = ll;
}

// ---------------------------------------------------------------------------
// Launch
// ---------------------------------------------------------------------------
extern "C" void kernel_launch(void* const* d_in, const int* in_sizes, int n_in,
                              void* d_out, int out_size)
{
    const float* x      = (const float*)d_in[0];
    const float* w_qkv  = (const float*)d_in[1];
    const float* conv_w = (const float*)d_in[2];
    const float* conv_b = (const float*)d_in[3];
    const float* gamma  = (const float*)d_in[4];
    const float* beta   = (const float*)d_in[5];
    const float* w_out  = (const float*)d_in[6];
    const float* b_out  = (const float*)d_in[7];
    float* out = (float*)d_out;

    constexpr int SMEM128 = 1024 + 16384 * 2 + 128 * 128 * 2;   // 66560
    constexpr int SMEM64  = 1024 + 16384 * 2 + 64 * 128 * 2;    // 50176
    cudaFuncSetAttribute(tc_gemm<128, 0>,
        cudaFuncAttributeMaxDynamicSharedMemorySize, SMEM128);
    cudaFuncSetAttribute(tc_gemm<128, 1>,
        cudaFuncAttributeMaxDynamicSharedMemorySize, SMEM128);
    cudaFuncSetAttribute(tc_gemm<128, 2>,
        cudaFuncAttributeMaxDynamicSharedMemorySize, SMEM128);
    cudaFuncSetAttribute(tc_gemm<64, 0>,
        cudaFuncAttributeMaxDynamicSharedMemorySize, SMEM64);

    void *p_xh, *p_xl, *p_wqh, *p_wql, *p_woh, *p_wol;
    void *p_qh, *p_ql, *p_attn, *p_ch, *p_cl, *p_vth, *p_vtl;
    void *p_u, *p_yh, *p_yl;
    cudaGetSymbolAddress(&p_xh,  g_xh);  cudaGetSymbolAddress(&p_xl,  g_xl);
    cudaGetSymbolAddress(&p_wqh, g_wqh); cudaGetSymbolAddress(&p_wql, g_wql);
    cudaGetSymbolAddress(&p_woh, g_woh); cudaGetSymbolAddress(&p_wol, g_wol);
    cudaGetSymbolAddress(&p_qh,  g_qkvh); cudaGetSymbolAddress(&p_ql, g_qkvl);
    cudaGetSymbolAddress(&p_attn, g_attn);
    cudaGetSymbolAddress(&p_ch,  g_ch);  cudaGetSymbolAddress(&p_cl,  g_cl);
    cudaGetSymbolAddress(&p_vth, g_vth); cudaGetSymbolAddress(&p_vtl, g_vtl);
    cudaGetSymbolAddress(&p_u,   g_u);
    cudaGetSymbolAddress(&p_yh,  g_yh);  cudaGetSymbolAddress(&p_yl,  g_yl);

    // 0) Operand conversions
    splitf_kernel<<<(KB * KN * KD) / 256, 256>>>(x, (bf16*)p_xh, (bf16*)p_xl,
                                                 KB * KN * KD);
    tsplit_kernel<<<dim3(KQ / 32, KD / 32), dim3(32, 8)>>>(
        w_qkv, (bf16*)p_wqh, (bf16*)p_wql, KD, KQ);
    tsplit_kernel<<<dim3(KD / 32, KD / 32), dim3(32, 8)>>>(
        w_out, (bf16*)p_woh, (bf16*)p_wol, KD, KD);

    // 1) QKV: [8192,1536] = x @ w_qkv  -> bf16 pair output
    tc_gemm<128, 2><<<dim3(KQ / 128, (KB * KN) / 128, 1), 256, SMEM128>>>(
        (const bf16*)p_xh, (const bf16*)p_xl,
        (const bf16*)p_wqh, (const bf16*)p_wql,
        nullptr, (bf16*)p_qh, (bf16*)p_ql, nullptr,
        KD, KD, KD, KQ,
        1, 0, 0, 0, 0, 0, 0, 1.0f);

    // 2) Logits per (b,h): A = 0.125 * Q @ K^T -> fp32
    tc_gemm<128, 0><<<dim3(KN / 128, KN / 128, KB * KH), 256, SMEM128>>>(
        (const bf16*)p_qh, (const bf16*)p_ql,
        (const bf16*)p_qh + 512, (const bf16*)p_ql + 512,
        (float*)p_attn, nullptr, nullptr, nullptr,
        KDH, KQ, KQ, KN,
        KH, (long)KN * KQ, 64, (long)KN * KQ, 64,
        (long)KH * KN * KN, (long)KN * KN, 0.125f);

    // 3) Fused softmax + conv head-mix (bf16 pair out) + cross moments
    smconv_kernel<<<KB * KN, 256>>>(conv_w);

    // 4) Stats path + V^T
    reduce_kernel<<<36, 256>>>();
    vsum_kernel<<<KB * KH, 256>>>();
    stats_kernel<<<1, 32>>>(conv_w, conv_b, gamma, beta);
    vtrans_kernel<<<dim3(KN / 32, KDH / 32, KB * KH), dim3(32, 8)>>>();

    // 5) U[b,h] = C[b,h] @ V[b,h]  (M=1024, N=64, K=1024) -> fp32
    tc_gemm<64, 0><<<dim3(1, KN / 128, KB * KH), 256, SMEM64>>>(
        (const bf16*)p_ch, (const bf16*)p_cl,
        (const bf16*)p_vth, (const bf16*)p_vtl,
        (float*)p_u, nullptr, nullptr, nullptr,
        KN, KN, KN, KDH,
        KH, (long)KH * KN * KN, (long)KN * KN,
        (long)KH * KDH * KN, (long)KDH * KN,
        (long)KH * KN * KDH, (long)KN * KDH, 1.0f);

    // 6) Assemble Y (deferred BN affine) -> bf16 pair
    assemble_kernel<<<(KB * KN * KD) / 256, 256>>>();

    // 7) out = Y @ w_out + b_out
    tc_gemm<128, 1><<<dim3(KD / 128, (KB * KN) / 128, 1), 256, SMEM128>>>(
        (const bf16*)p_yh, (const bf16*)p_yl,
        (const bf16*)p_woh, (const bf16*)p_wol,
        out, nullptr, nullptr, b_out,
        KD, KD, KD, KD,
        1, 0, 0, 0, 0, 0, 0, 1.0f);
}

// round 9
// speedup vs baseline: 2.3001x; 1.7197x over previous
#include <cuda_runtime.h>
#include <cuda_bf16.h>
#include <math.h>
#include <cstdint>

// Problem constants
#define KB   8      // batch
#define KN   1024   // sequence length
#define KD   512    // model dim
#define KH   8      // heads
#define KDH  64     // dim per head
#define KQ   1536   // qkv columns

typedef __nv_bfloat16 bf16;
typedef __nv_bfloat162 bf162;

// ---------------------------------------------------------------------------
// Scratch (static __device__ arrays; allocation-free per harness rules)
// ---------------------------------------------------------------------------
__device__ __align__(16) bf16  g_xh [KB * KN * KD];           // x split hi
__device__ __align__(16) bf16  g_xl [KB * KN * KD];           // x split lo
__device__ __align__(16) bf16  g_wqh[KQ * KD];                // w_qkv^T hi
__device__ __align__(16) bf16  g_wql[KQ * KD];
__device__ __align__(16) bf16  g_woh[KD * KD];                // w_out^T hi
__device__ __align__(16) bf16  g_wol[KD * KD];
__device__ __align__(16) bf16  g_qkvh[KB * KN * KQ];          // qkv split hi
__device__ __align__(16) bf16  g_qkvl[KB * KN * KQ];
__device__ __align__(16) float g_attn[KB * KH * KN * KN];     // raw logits (fp32)
__device__ __align__(16) bf16  g_ch [KB * KH * KN * KN];      // C = conv-mix, hi
__device__ __align__(16) bf16  g_cl [KB * KH * KN * KN];      // C lo
__device__ __align__(16) bf16  g_vth[KB * KH * KDH * KN];     // V^T [bh, d, m] hi
__device__ __align__(16) bf16  g_vtl[KB * KH * KDH * KN];
__device__ __align__(16) float g_u  [KB * KH * KN * KDH];     // U = C @ V (fp32)
__device__ __align__(16) bf16  g_yh [KB * KN * KD];           // Y split hi
__device__ __align__(16) bf16  g_yl [KB * KN * KD];
__device__ __align__(16) float g_vsum[KB * KH * KDH];
__device__ __align__(16) float g_part[KB * KN * 36];
__device__ __align__(16) float g_S  [36];
__device__ float g_k0[KH];
__device__ float g_k1[KH];

// ---------------------------------------------------------------------------
// Helpers
// ---------------------------------------------------------------------------
__device__ __forceinline__ uint32_t smem_u32(const void* p) {
    uint32_t a;
    asm("{ .reg .u64 t; cvta.to.shared.u64 t, %1; cvt.u32.u64 %0, t; }"
        : "=r"(a) : "l"(p));
    return a;
}
#define SW128(x) ((x) ^ (((x) >> 3) & 0x70))

__device__ __forceinline__ void split_bf(float v, bf16& h, bf16& l) {
    h = __float2bfloat16(v);
    l = __float2bfloat16(v - __bfloat162float(h));
}

// ldmatrix x4 (b16)
__device__ __forceinline__ void ldsm4(uint32_t addr, uint32_t* r) {
    asm volatile("ldmatrix.sync.aligned.m8n8.x4.shared.b16 {%0,%1,%2,%3}, [%4];"
                 : "=r"(r[0]), "=r"(r[1]), "=r"(r[2]), "=r"(r[3]) : "r"(addr));
}
// mma m16n8k16 bf16 -> f32 accumulate
__device__ __forceinline__ void mma16816(float* c, const uint32_t* a,
                                         uint32_t b0, uint32_t b1) {
    asm volatile(
        "mma.sync.aligned.m16n8k16.row.col.f32.bf16.bf16.f32 "
        "{%0,%1,%2,%3}, {%4,%5,%6,%7}, {%8,%9}, {%0,%1,%2,%3};"
        : "+f"(c[0]), "+f"(c[1]), "+f"(c[2]), "+f"(c[3])
        : "r"(a[0]), "r"(a[1]), "r"(a[2]), "r"(a[3]), "r"(b0), "r"(b1));
}
// 16-byte async copy global -> shared
__device__ __forceinline__ void cpasync16(uint32_t s, const void* g) {
    asm volatile("cp.async.cg.shared.global [%0], [%1], 16;"
                 :: "r"(s), "l"(g));
}
#define CP_COMMIT()  asm volatile("cp.async.commit_group;" ::: "memory")
#define CP_WAIT0()   asm volatile("cp.async.wait_group 0;" ::: "memory")
#define CP_WAIT1()   asm volatile("cp.async.wait_group 1;" ::: "memory")

// ---------------------------------------------------------------------------
// bf16x2-split GEMM with 2-stage cp.async pipeline.
//   D[128 x BN] = alpha * A @ B^T (+bias)
//   A rows K-major (bf16 hi/lo), B rows K-major (B[n][k]). K multiple of 64.
//   MODE 0: fp32 out *alpha; 1: fp32 *alpha + bias; 2: bf16 hi/lo pair out.
// ---------------------------------------------------------------------------
template <int BN, int MODE>
__global__ __launch_bounds__(256, 1)
void tc_gemm(const bf16* __restrict__ Ah, const bf16* __restrict__ Al,
             const bf16* __restrict__ Bh, const bf16* __restrict__ Bl,
             float* __restrict__ Cf, bf16* __restrict__ Ch,
             bf16* __restrict__ Cl, const float* __restrict__ bias,
             int K, int lda, int ldb, int ldc,
             int HB, long sA1, long sA2, long sB1, long sB2,
             long sC1, long sC2, float alpha)
{
    extern __shared__ __align__(1024) char smem[];
    constexpr int STAGE = 32768 + BN * 256;   // AH(16K)+AL(16K)+BH+BL
    constexpr int OFF0  = 1024;

    const uint32_t sb = smem_u32(smem);
    const int tid = threadIdx.x, wid = tid >> 5, lane = tid & 31;
    const int z = blockIdx.z;
    const long zq = z / HB, zr = z % HB;
    const bf16* pAh = Ah + zq * sA1 + zr * sA2;
    const bf16* pAl = Al + zq * sA1 + zr * sA2;
    const bf16* pBh = Bh + zq * sB1 + zr * sB2;
    const bf16* pBl = Bl + zq * sB1 + zr * sB2;
    const int row0 = blockIdx.y * 128;
    const int col0 = blockIdx.x * BN;
    const int nch = K >> 6;

    constexpr int WNT = BN / 2;          // warp n-tile width (64 or 32)
    constexpr int NI  = WNT / 8;         // n 16x8 tiles per warp
    constexpr int NPT = WNT / 16;        // ldmatrix.x4 pairs per warp
    const int wr = wid & 3;              // row group (32 rows)
    const int wc = wid >> 2;             // col group

    float acc[2][NI][4];
#pragma unroll
    for (int mi = 0; mi < 2; mi++)
#pragma unroll
        for (int ni = 0; ni < NI; ni++)
#pragma unroll
            for (int e = 0; e < 4; e++) acc[mi][ni][e] = 0.f;

    const int arow = lane & 15;
    const int akb  = (lane >> 4) << 4;
    const int brow = ((lane >> 4) << 3) + (lane & 7);
    const int bkb  = ((lane >> 3) & 1) << 4;

    // --- async stage loader: chunk ch -> stage st ---
    auto issue_chunk = [&](int st, int ch) {
        const int kt = ch << 6;
        const uint32_t base = sb + OFF0 + st * STAGE;
        for (int i = tid; i < 128 * 8; i += 256) {
            int r = i >> 3, c = (i & 7) * 16;
            uint32_t so = SW128(r * 128 + c);
            long gi = (long)(row0 + r) * lda + kt + (c >> 1);
            cpasync16(base + so, pAh + gi);
            cpasync16(base + 16384 + so, pAl + gi);
        }
        for (int i = tid; i < BN * 8; i += 256) {
            int r = i >> 3, c = (i & 7) * 16;
            uint32_t so = SW128(r * 128 + c);
            long gi = (long)(col0 + r) * ldb + kt + (c >> 1);
            cpasync16(base + 32768 + so, pBh + gi);
            cpasync16(base + 32768 + BN * 128 + so, pBl + gi);
        }
        CP_COMMIT();
    };

    issue_chunk(0, 0);

    for (int ch = 0; ch < nch; ch++) {
        const int cur = ch & 1;
        const bool pf = (ch + 1 < nch);
        if (pf) issue_chunk((ch + 1) & 1, ch + 1);
        if (pf) CP_WAIT1(); else CP_WAIT0();
        __syncthreads();

        const uint32_t OAH = sb + OFF0 + cur * STAGE;
        const uint32_t OAL = OAH + 16384;
        const uint32_t OBH = OAH + 32768;
        const uint32_t OBL = OBH + BN * 128;

#pragma unroll
        for (int k16 = 0; k16 < 4; k16++) {
            uint32_t ah[2][4], al2[2][4];
#pragma unroll
            for (int mi = 0; mi < 2; mi++) {
                uint32_t off = SW128((wr * 32 + mi * 16 + arow) * 128 +
                                     k16 * 32 + akb);
                ldsm4(OAH + off, ah[mi]);
                ldsm4(OAL + off, al2[mi]);
            }
            uint32_t bh2[NPT][4], bl2[NPT][4];
#pragma unroll
            for (int np = 0; np < NPT; np++) {
                uint32_t off = SW128((wc * WNT + np * 16 + brow) * 128 +
                                     k16 * 32 + bkb);
                ldsm4(OBH + off, bh2[np]);
                ldsm4(OBL + off, bl2[np]);
            }
#pragma unroll
            for (int mi = 0; mi < 2; mi++)
#pragma unroll
                for (int np = 0; np < NPT; np++) {
                    mma16816(acc[mi][2 * np], ah[mi], bh2[np][0], bh2[np][1]);
                    mma16816(acc[mi][2 * np], ah[mi], bl2[np][0], bl2[np][1]);
                    mma16816(acc[mi][2 * np], al2[mi], bh2[np][0], bh2[np][1]);
                    mma16816(acc[mi][2 * np + 1], ah[mi], bh2[np][2], bh2[np][3]);
                    mma16816(acc[mi][2 * np + 1], ah[mi], bl2[np][2], bl2[np][3]);
                    mma16816(acc[mi][2 * np + 1], al2[mi], bh2[np][2], bh2[np][3]);
                }
        }
        __syncthreads();
    }

    // Epilogue: c0=(m=qrow,n=qcol), c1=(m,n+1), c2=(m+8,n), c3=(m+8,n+1)
    const int qrow = lane >> 2;
    const int qcol = (lane & 3) * 2;
#pragma unroll
    for (int mi = 0; mi < 2; mi++) {
        const long rb = row0 + wr * 32 + mi * 16 + qrow;
#pragma unroll
        for (int ni = 0; ni < NI; ni++) {
            const int c = col0 + wc * WNT + ni * 8 + qcol;
            float v0 = acc[mi][ni][0] * alpha;
            float v1 = acc[mi][ni][1] * alpha;
            float v2 = acc[mi][ni][2] * alpha;
            float v3 = acc[mi][ni][3] * alpha;
            if (MODE == 1) {
                v0 += bias[c]; v1 += bias[c + 1];
                v2 += bias[c]; v3 += bias[c + 1];
            }
            if (MODE == 0 || MODE == 1) {
                float* pC = Cf + zq * sC1 + zr * sC2;
                float2 w0; w0.x = v0; w0.y = v1;
                float2 w1; w1.x = v2; w1.y = v3;
                *(float2*)&pC[rb * ldc + c] = w0;
                *(float2*)&pC[(rb + 8) * ldc + c] = w1;
            } else {
                bf16* pH = Ch + zq * sC1 + zr * sC2;
                bf16* pL = Cl + zq * sC1 + zr * sC2;
                bf16 h0, l0, h1, l1, h2, l2, h3, l3;
                split_bf(v0, h0, l0); split_bf(v1, h1, l1);
                split_bf(v2, h2, l2); split_bf(v3, h3, l3);
                bf162 ha; ha.x = h0; ha.y = h1;
                bf162 hb; hb.x = h2; hb.y = h3;
                bf162 la; la.x = l0; la.y = l1;
                bf162 lb; lb.x = l2; lb.y = l3;
                *(bf162*)&pH[rb * ldc + c] = ha;
                *(bf162*)&pL[rb * ldc + c] = la;
                *(bf162*)&pH[(rb + 8) * ldc + c] = hb;
                *(bf162*)&pL[(rb + 8) * ldc + c] = lb;
            }
        }
    }
}

// ---------------------------------------------------------------------------
// Conversion / transpose kernels
// ---------------------------------------------------------------------------
__global__ __launch_bounds__(256)
void splitf_kernel(const float* __restrict__ in, bf16* __restrict__ oh,
                   bf16* __restrict__ ol, int n)
{
    int i = blockIdx.x * 256 + threadIdx.x;
    if (i < n) {
        bf16 h, l;
        split_bf(in[i], h, l);
        oh[i] = h; ol[i] = l;
    }
}

// out[c, r] = split(in[r, c]); in is R x C row-major. Grid (C/32, R/32), blk (32,8)
__global__ __launch_bounds__(256)
void tsplit_kernel(const float* __restrict__ in, bf16* __restrict__ oh,
                   bf16* __restrict__ ol, int R, int C)
{
    __shared__ float t[32][33];
    int c0 = blockIdx.x * 32, r0 = blockIdx.y * 32;
    for (int i = threadIdx.y; i < 32; i += 8)
        t[i][threadIdx.x] = in[(long)(r0 + i) * C + c0 + threadIdx.x];
    __syncthreads();
    for (int i = threadIdx.y; i < 32; i += 8) {
        float v = t[threadIdx.x][i];
        long o = (long)(c0 + i) * R + r0 + threadIdx.x;
        bf16 h, l;
        split_bf(v, h, l);
        oh[o] = h; ol[o] = l;
    }
}

// V^T: g_vt[bh, d, m] = qkv pair [b, m, 1024 + h*64 + d].
__global__ __launch_bounds__(256)
void vtrans_kernel()
{
    __shared__ bf16 th[32][40], tl[32][40];
    const int bh = blockIdx.z;
    const int b = bh >> 3, h = bh & 7;
    const int m0 = blockIdx.x * 32, d0 = blockIdx.y * 32;
    const bf16* ih = g_qkvh + (long)b * KN * KQ + 1024 + h * 64 + d0;
    const bf16* il = g_qkvl + (long)b * KN * KQ + 1024 + h * 64 + d0;
    for (int i = threadIdx.y; i < 32; i += 8) {
        th[i][threadIdx.x] = ih[(long)(m0 + i) * KQ + threadIdx.x];
        tl[i][threadIdx.x] = il[(long)(m0 + i) * KQ + threadIdx.x];
    }
    __syncthreads();
    bf16* oh = g_vth + ((long)bh * KDH + d0) * KN + m0;
    bf16* ol = g_vtl + ((long)bh * KDH + d0) * KN + m0;
    for (int i = threadIdx.y; i < 32; i += 8) {
        oh[(long)i * KN + threadIdx.x] = th[threadIdx.x][i];
        ol[(long)i * KN + threadIdx.x] = tl[threadIdx.x][i];
    }
}

// ---------------------------------------------------------------------------
// Fused per-(b,n): softmax (8 heads) + conv head-mix (-> bf16 pairs) + moments
// ---------------------------------------------------------------------------
__global__ __launch_bounds__(256)
void smconv_kernel(const float* __restrict__ cw)
{
    __shared__ __align__(16) float sa[KH][KN];
    __shared__ float sinv[KH];
    __shared__ float scw[64];
    __shared__ float red[8][36];

    const int bidx = blockIdx.x;
    const int b = bidx >> 10;
    const int n = bidx & (KN - 1);
    const long hs = (long)KN * KN;
    const float* base = g_attn + (long)b * KH * hs + (long)n * KN;
    bf16* chb = g_ch + (long)b * KH * hs + (long)n * KN;
    bf16* clb = g_cl + (long)b * KH * hs + (long)n * KN;

    const int tid = threadIdx.x;

    for (int i = tid; i < KH * KN / 4; i += 256) {
        int h = i >> 8;
        int m4 = (i & 255) * 4;
        *reinterpret_cast<float4*>(&sa[h][m4]) =
            *reinterpret_cast<const float4*>(&base[(long)h * hs + m4]);
    }
    __syncthreads();

    {
        const int w = tid >> 5, lane = tid & 31;
        float vmax = -1e30f;
        for (int i = lane; i < KN; i += 32) vmax = fmaxf(vmax, sa[w][i]);
#pragma unroll
        for (int o = 16; o; o >>= 1)
            vmax = fmaxf(vmax, __shfl_xor_sync(0xffffffffu, vmax, o));
        float s = 0.f;
        for (int i = lane; i < KN; i += 32) {
            float e = __expf(sa[w][i] - vmax);
            sa[w][i] = e;
            s += e;
        }
#pragma unroll
        for (int o = 16; o; o >>= 1) s += __shfl_xor_sync(0xffffffffu, s, o);
        if (lane == 0) sinv[w] = 1.0f / s;
    }
    __syncthreads();
    if (tid < 64) scw[tid] = cw[tid] * sinv[tid & 7];
    __syncthreads();

    const int m0 = tid * 4;
    float4 av[KH];
#pragma unroll
    for (int h = 0; h < KH; h++)
        av[h] = *reinterpret_cast<const float4*>(&sa[h][m0]);

    float s36[36];
#pragma unroll
    for (int p = 0; p < 36; p++) s36[p] = 0.f;
    float cv[KH][4];

#pragma unroll
    for (int e = 0; e < 4; e++) {
        float a8[KH];
#pragma unroll
        for (int h = 0; h < KH; h++)
            a8[h] = (e == 0) ? av[h].x : (e == 1) ? av[h].y
                   : (e == 2) ? av[h].z : av[h].w;
        int p = 0;
#pragma unroll
        for (int h = 0; h < KH; h++)
#pragma unroll
            for (int h2 = h; h2 < KH; h2++) s36[p++] += a8[h] * a8[h2];
#pragma unroll
        for (int g = 0; g < KH; g++) {
            float c = 0.f;
#pragma unroll
            for (int h = 0; h < KH; h++) c += scw[g * 8 + h] * a8[h];
            cv[g][e] = c;
        }
    }
#pragma unroll
    for (int g = 0; g < KH; g++) {
        bf16 h0, l0, h1, l1, h2, l2, h3, l3;
        split_bf(cv[g][0], h0, l0);
        split_bf(cv[g][1], h1, l1);
        split_bf(cv[g][2], h2, l2);
        split_bf(cv[g][3], h3, l3);
        bf162 ha; ha.x = h0; ha.y = h1;
        bf162 hb; hb.x = h2; hb.y = h3;
        bf162 la; la.x = l0; la.y = l1;
        bf162 lb; lb.x = l2; lb.y = l3;
        *(bf162*)&chb[(long)g * hs + m0]     = ha;
        *(bf162*)&chb[(long)g * hs + m0 + 2] = hb;
        *(bf162*)&clb[(long)g * hs + m0]     = la;
        *(bf162*)&clb[(long)g * hs + m0 + 2] = lb;
    }

    const int lane = tid & 31, warp = tid >> 5;
#pragma unroll
    for (int p = 0; p < 36; p++) {
        float v = s36[p];
#pragma unroll
        for (int o = 16; o; o >>= 1) v += __shfl_xor_sync(0xffffffffu, v, o);
        if (lane == 0) red[warp][p] = v;
    }
    __syncthreads();
    if (tid < 36) {
        float v = 0.f;
#pragma unroll
        for (int w = 0; w < 8; w++) v += red[w][tid];
        int h = 0, rem = tid;
        while (rem >= KH - h) { rem -= KH - h; h++; }
        int h2 = h + rem;
        g_part[(long)bidx * 36 + tid] = v * sinv[h] * sinv[h2];
    }
}

// Deterministic reduction of moment partials -> g_S (means).
__global__ __launch_bounds__(256)
void reduce_kernel()
{
    const int p = blockIdx.x;
    float v = 0.f;
    for (int i = threadIdx.x; i < KB * KN; i += 256)
        v += g_part[(long)i * 36 + p];
    __shared__ float sm[256];
    sm[threadIdx.x] = v;
    __syncthreads();
    for (int o = 128; o; o >>= 1) {
        if (threadIdx.x < o) sm[threadIdx.x] += sm[threadIdx.x + o];
        __syncthreads();
    }
    if (threadIdx.x == 0) g_S[p] = sm[0] * (1.0f / 8388608.0f);
}

// Vsum[b,h,d] = sum_m V[b,h,m,d] (from bf16 pairs).
__global__ __launch_bounds__(256)
void vsum_kernel()
{
    const int bh = blockIdx.x;
    const int t = threadIdx.x;
    const int d = t & 63;
    const int q = t >> 6;
    const int b = bh >> 3, h = bh & 7;
    const bf16* ph = g_qkvh + (long)b * KN * KQ + 1024 + h * 64 + d;
    const bf16* pl = g_qkvl + (long)b * KN * KQ + 1024 + h * 64 + d;
    float s = 0.f;
    for (int m = q * 256; m < (q + 1) * 256; m++)
        s += __bfloat162float(ph[(long)m * KQ]) + __bfloat162float(pl[(long)m * KQ]);
    __shared__ float sm[256];
    sm[t] = s;
    __syncthreads();
    if (q == 0)
        g_vsum[bh * 64 + d] = sm[d] + sm[64 + d] + sm[128 + d] + sm[192 + d];
}

// BatchNorm coefficients from analytic mean + cross moments.
__global__ void stats_kernel(const float* __restrict__ cw,
                             const float* __restrict__ cb,
                             const float* __restrict__ gamma,
                             const float* __restrict__ beta)
{
    int g = threadIdx.x;
    if (g >= KH) return;
    float Sf[8][8];
    int p = 0;
    for (int h = 0; h < 8; h++)
        for (int h2 = h; h2 < 8; h2++) {
            float v = g_S[p++];
            Sf[h][h2] = v; Sf[h2][h] = v;
        }
    float meanC = 0.f;
    for (int h = 0; h < 8; h++) meanC += cw[g * 8 + h];
    meanC *= (1.0f / KN);
    float mean = meanC + cb[g];
    float e2 = cb[g] * cb[g] + 2.f * cb[g] * meanC;
    for (int h = 0; h < 8; h++)
        for (int h2 = 0; h2 < 8; h2++)
            e2 += cw[g * 8 + h] * cw[g * 8 + h2] * Sf[h][h2];
    float var = e2 - mean * mean;
    float s = gamma[g] * rsqrtf(var + 1e-5f);
    g_k1[g] = s;
    g_k0[g] = beta[g] - s * meanC;
}

// Y[b,n,h*64+d] = k1[h]*U[b,h,n,d] + k0[h]*Vsum[b,h,d], split to bf16 pair
__global__ __launch_bounds__(256)
void assemble_kernel()
{
    int i = blockIdx.x * 256 + threadIdx.x;
    int c = i & 511;
    int h = c >> 6;
    int d = c & 63;
    int bn = i >> 9;
    int n = bn & (KN - 1);
    int b = bn >> 10;
    long ui = ((((long)b * KH + h) * KN) + n) * KDH + d;
    float v = g_k1[h] * g_u[ui] + g_k0[h] * g_vsum[(b * KH + h) * KDH + d];
    bf16 hh, ll;
    split_bf(v, hh, ll);
    g_yh[i] = hh; g_yl[i] = ll;
}

// ---------------------------------------------------------------------------
// Launch
// ---------------------------------------------------------------------------
extern "C" void kernel_launch(void* const* d_in, const int* in_sizes, int n_in,
                              void* d_out, int out_size)
{
    const float* x      = (const float*)d_in[0];
    const float* w_qkv  = (const float*)d_in[1];
    const float* conv_w = (const float*)d_in[2];
    const float* conv_b = (const float*)d_in[3];
    const float* gamma  = (const float*)d_in[4];
    const float* beta   = (const float*)d_in[5];
    const float* w_out  = (const float*)d_in[6];
    const float* b_out  = (const float*)d_in[7];
    float* out = (float*)d_out;

    constexpr int SMEM128 = 1024 + 2 * (32768 + 128 * 256);   // 132096
    constexpr int SMEM64  = 1024 + 2 * (32768 + 64 * 256);    //  99328
    cudaFuncSetAttribute(tc_gemm<128, 0>,
        cudaFuncAttributeMaxDynamicSharedMemorySize, SMEM128);
    cudaFuncSetAttribute(tc_gemm<128, 1>,
        cudaFuncAttributeMaxDynamicSharedMemorySize, SMEM128);
    cudaFuncSetAttribute(tc_gemm<128, 2>,
        cudaFuncAttributeMaxDynamicSharedMemorySize, SMEM128);
    cudaFuncSetAttribute(tc_gemm<64, 0>,
        cudaFuncAttributeMaxDynamicSharedMemorySize, SMEM64);

    void *p_xh, *p_xl, *p_wqh, *p_wql, *p_woh, *p_wol;
    void *p_qh, *p_ql, *p_attn, *p_ch, *p_cl, *p_vth, *p_vtl;
    void *p_u, *p_yh, *p_yl;
    cudaGetSymbolAddress(&p_xh,  g_xh);  cudaGetSymbolAddress(&p_xl,  g_xl);
    cudaGetSymbolAddress(&p_wqh, g_wqh); cudaGetSymbolAddress(&p_wql, g_wql);
    cudaGetSymbolAddress(&p_woh, g_woh); cudaGetSymbolAddress(&p_wol, g_wol);
    cudaGetSymbolAddress(&p_qh,  g_qkvh); cudaGetSymbolAddress(&p_ql, g_qkvl);
    cudaGetSymbolAddress(&p_attn, g_attn);
    cudaGetSymbolAddress(&p_ch,  g_ch);  cudaGetSymbolAddress(&p_cl,  g_cl);
    cudaGetSymbolAddress(&p_vth, g_vth); cudaGetSymbolAddress(&p_vtl, g_vtl);
    cudaGetSymbolAddress(&p_u,   g_u);
    cudaGetSymbolAddress(&p_yh,  g_yh);  cudaGetSymbolAddress(&p_yl,  g_yl);

    // 0) Operand conversions
    splitf_kernel<<<(KB * KN * KD) / 256, 256>>>(x, (bf16*)p_xh, (bf16*)p_xl,
                                                 KB * KN * KD);
    tsplit_kernel<<<dim3(KQ / 32, KD / 32), dim3(32, 8)>>>(
        w_qkv, (bf16*)p_wqh, (bf16*)p_wql, KD, KQ);
    tsplit_kernel<<<dim3(KD / 32, KD / 32), dim3(32, 8)>>>(
        w_out, (bf16*)p_woh, (bf16*)p_wol, KD, KD);

    // 1) QKV: [8192,1536] = x @ w_qkv  -> bf16 pair output
    tc_gemm<128, 2><<<dim3(KQ / 128, (KB * KN) / 128, 1), 256, SMEM128>>>(
        (const bf16*)p_xh, (const bf16*)p_xl,
        (const bf16*)p_wqh, (const bf16*)p_wql,
        nullptr, (bf16*)p_qh, (bf16*)p_ql, nullptr,
        KD, KD, KD, KQ,
        1, 0, 0, 0, 0, 0, 0, 1.0f);

    // 2) Logits per (b,h): A = 0.125 * Q @ K^T -> fp32
    tc_gemm<128, 0><<<dim3(KN / 128, KN / 128, KB * KH), 256, SMEM128>>>(
        (const bf16*)p_qh, (const bf16*)p_ql,
        (const bf16*)p_qh + 512, (const bf16*)p_ql + 512,
        (float*)p_attn, nullptr, nullptr, nullptr,
        KDH, KQ, KQ, KN,
        KH, (long)KN * KQ, 64, (long)KN * KQ, 64,
        (long)KH * KN * KN, (long)KN * KN, 0.125f);

    // 3) Fused softmax + conv head-mix (bf16 pair out) + cross moments
    smconv_kernel<<<KB * KN, 256>>>(conv_w);

    // 4) Stats path + V^T
    reduce_kernel<<<36, 256>>>();
    vsum_kernel<<<KB * KH, 256>>>();
    stats_kernel<<<1, 32>>>(conv_w, conv_b, gamma, beta);
    vtrans_kernel<<<dim3(KN / 32, KDH / 32, KB * KH), dim3(32, 8)>>>();

    // 5) U[b,h] = C[b,h] @ V[b,h]  (M=1024, N=64, K=1024) -> fp32
    tc_gemm<64, 0><<<dim3(1, KN / 128, KB * KH), 256, SMEM64>>>(
        (const bf16*)p_ch, (const bf16*)p_cl,
        (const bf16*)p_vth, (const bf16*)p_vtl,
        (float*)p_u, nullptr, nullptr, nullptr,
        KN, KN, KN, KDH,
        KH, (long)KH * KN * KN, (long)KN * KN,
        (long)KH * KDH * KN, (long)KDH * KN,
        (long)KH * KN * KDH, (long)KN * KDH, 1.0f);

    // 6) Assemble Y (deferred BN affine) -> bf16 pair
    assemble_kernel<<<(KB * KN * KD) / 256, 256>>>();

    // 7) out = Y @ w_out + b_out
    tc_gemm<128, 1><<<dim3(KD / 128, (KB * KN) / 128, 1), 256, SMEM128>>>(
        (const bf16*)p_yh, (const bf16*)p_yl,
        (const bf16*)p_woh, (const bf16*)p_wol,
        out, nullptr, nullptr, b_out,
        KD, KD, KD, KD,
        1, 0, 0, 0, 0, 0, 0, 1.0f);
}